// round 7
// baseline (speedup 1.0000x reference)
#include <cuda_runtime.h>
#include <math.h>

#define BATCH 4
#define INCH 256
#define SKIPCH 64
#define EMBEDC 64
#define NPIX 4096   // 64*64

// ---------------- scratch (static device globals; no allocation) ----------------
__device__ float g_skipu[BATCH*SKIPCH*NPIX];
__device__ float g_mean [BATCH*NPIX];
__device__ float g_thick[BATCH*NPIX];
__device__ float g_qkv  [BATCH*96*NPIX];
__device__ float g_av   [BATCH*32*NPIX];
__device__ float g_x2   [BATCH*INCH*NPIX];
__device__ float g_edge [BATCH*SKIPCH*NPIX];
__device__ float g_col  [BATCH*576*NPIX];   // im2col(edge), then reused for sampled vals
__device__ float g_off  [BATCH*32*NPIX];    // 18 used, padded to 32
__device__ float g_offw [32*576];
__device__ float g_offb [32];
__device__ float g_d    [BATCH*SKIPCH*NPIX];
__device__ float g_e    [BATCH*EMBEDC*NPIX];
__device__ float g_ln   [BATCH*EMBEDC*NPIX];
__device__ float g_h1   [BATCH*256*NPIX];
__device__ float g_h2   [BATCH*256*NPIX];
__device__ float g_t    [BATCH*EMBEDC*NPIX];

__device__ __forceinline__ float gelu_f(float v) {
    return 0.5f * v * (1.0f + erff(v * 0.70710678118654752f));
}

__device__ __forceinline__ float tf32f(float x) {
    unsigned u;
    asm("cvt.rna.tf32.f32 %0, %1;" : "=r"(u) : "f"(x));
    return __uint_as_float(u);
}

__device__ __forceinline__ void mma_tf32(float* d, const float* a, float b0, float b1) {
    asm volatile("mma.sync.aligned.m16n8k8.row.col.f32.tf32.tf32.f32 "
        "{%0,%1,%2,%3}, {%4,%5,%6,%7}, {%8,%9}, {%0,%1,%2,%3};"
        : "+f"(d[0]), "+f"(d[1]), "+f"(d[2]), "+f"(d[3])
        : "r"(__float_as_uint(a[0])), "r"(__float_as_uint(a[1])),
          "r"(__float_as_uint(a[2])), "r"(__float_as_uint(a[3])),
          "r"(__float_as_uint(b0)), "r"(__float_as_uint(b1)));
}

// ---------------- bilinear upsample (half-pixel, clamp) + channel mean + thick ----------------
__global__ void k_upsample(const float* __restrict__ skip, const float* __restrict__ thick_w,
                           const float* __restrict__ thick_b,
                           float* __restrict__ skipu, float* __restrict__ meanv,
                           float* __restrict__ thick)
{
    int idx = blockIdx.x * blockDim.x + threadIdx.x;
    if (idx >= BATCH * NPIX) return;
    int b = idx >> 12, p = idx & 4095;
    int oy = p >> 6, ox = p & 63;
    float sy = oy * 0.5f - 0.25f, sx = ox * 0.5f - 0.25f;
    float y0f = floorf(sy), x0f = floorf(sx);
    float wy = sy - y0f, wx = sx - x0f;
    int y0 = (int)y0f, x0 = (int)x0f;
    int y0c = min(max(y0, 0), 31), y1c = min(max(y0 + 1, 0), 31);
    int x0c = min(max(x0, 0), 31), x1c = min(max(x0 + 1, 0), 31);
    float w00 = (1.f - wy) * (1.f - wx), w01 = (1.f - wy) * wx;
    float w10 = wy * (1.f - wx), w11 = wy * wx;
    const float* sb = skip + (size_t)b * SKIPCH * 1024;
    float s = 0.f, ta = 0.f;
    #pragma unroll 4
    for (int c = 0; c < SKIPCH; c++) {
        const float* pc = sb + c * 1024;
        float v = w00 * pc[y0c*32 + x0c] + w01 * pc[y0c*32 + x1c]
                + w10 * pc[y1c*32 + x0c] + w11 * pc[y1c*32 + x1c];
        skipu[((size_t)(b*SKIPCH + c)) * NPIX + p] = v;
        s += v;
        ta += v * thick_w[c];
    }
    meanv[idx] = s * (1.0f / 64.0f);
    thick[idx] = 1.0f / (1.0f + __expf(-(ta + thick_b[0])));
}

// ---------------- edge conv: 3x3, 1->64 ch, no bias, zero pad ----------------
__global__ void k_edge(const float* __restrict__ meanv, const float* __restrict__ edge_w,
                       float* __restrict__ edge)
{
    int idx = blockIdx.x * blockDim.x + threadIdx.x;
    if (idx >= BATCH * SKIPCH * NPIX) return;
    int p = idx & 4095, oc = (idx >> 12) & 63, b = idx >> 18;
    int y = p >> 6, x = p & 63;
    const float* mb = meanv + b * NPIX;
    const float* w = edge_w + oc * 9;
    float acc = 0.f;
    #pragma unroll
    for (int dy = -1; dy <= 1; dy++)
        #pragma unroll
        for (int dx = -1; dx <= 1; dx++) {
            int yy = y + dy, xx = x + dx;
            if ((unsigned)yy < 64u && (unsigned)xx < 64u)
                acc += mb[yy*64 + xx] * w[(dy+1)*3 + (dx+1)];
        }
    edge[idx] = acc;
}

// ---------------- im2col of edge: rows ic*9+tap ----------------
__global__ void k_im2col(const float* __restrict__ edge, float* __restrict__ col)
{
    int idx = blockIdx.x * blockDim.x + threadIdx.x;
    if (idx >= BATCH * 576 * NPIX) return;
    int p = idx & 4095;
    int r = (idx >> 12) % 576;
    int b = idx / (576 * NPIX);
    int ic = r / 9, tap = r % 9;
    int y = (p >> 6) + tap/3 - 1, x = (p & 63) + tap%3 - 1;
    float v = 0.f;
    if ((unsigned)y < 64u && (unsigned)x < 64u)
        v = edge[(((size_t)b*64 + ic) << 12) + y*64 + x];
    col[idx] = v;
}

// ---------------- pad off weights 18 -> 32 rows ----------------
__global__ void k_prep_offw(const float* __restrict__ off_w, const float* __restrict__ off_b,
                            float* __restrict__ wpad, float* __restrict__ bpad)
{
    int idx = blockIdx.x * blockDim.x + threadIdx.x;
    if (idx < 32 * 576) {
        int o = idx / 576, k = idx % 576;
        wpad[idx] = (o < 18) ? off_w[o*576 + k] : 0.f;
    }
    if (idx < 32) bpad[idx] = (idx < 18) ? off_b[idx] : 0.f;
}

// ---------------- deformable bilinear sampling (guide scale fused) ----------------
// dy,dx read from raw off and scaled by (1 + 16*thick) inline.
__global__ void k_sample(const float* __restrict__ off, const float* __restrict__ thick,
                         const float* __restrict__ skipu, float* __restrict__ col)
{
    int idx = blockIdx.x * blockDim.x + threadIdx.x;
    if (idx >= BATCH * 9 * NPIX) return;
    int p = idx & 4095;
    int k = (idx >> 12) % 9;
    int b = idx / (9 * NPIX);
    float guide = 1.f + 16.f * thick[b*NPIX + p];
    float dy = off[(((size_t)b*32 + 2*k    ) << 12) + p] * guide;
    float dx = off[(((size_t)b*32 + 2*k + 1) << 12) + p] * guide;
    float py = (float)(p >> 6) + (float)(k/3 - 1) + dy;
    float px = (float)(p & 63) + (float)(k%3 - 1) + dx;
    float y0f = floorf(py), x0f = floorf(px);
    float wy = py - y0f, wx = px - x0f;
    int y0 = (int)y0f, x0 = (int)x0f;
    int y1 = y0 + 1, x1 = x0 + 1;
    float vy0 = (y0 >= 0 && y0 < 64) ? 1.f : 0.f;
    float vy1 = (y1 >= 0 && y1 < 64) ? 1.f : 0.f;
    float vx0 = (x0 >= 0 && x0 < 64) ? 1.f : 0.f;
    float vx1 = (x1 >= 0 && x1 < 64) ? 1.f : 0.f;
    int y0c = min(max(y0,0),63), y1c = min(max(y1,0),63);
    int x0c = min(max(x0,0),63), x1c = min(max(x1,0),63);
    float w00 = (1.f-wy)*(1.f-wx)*vy0*vx0;
    float w01 = (1.f-wy)*wx      *vy0*vx1;
    float w10 = wy*(1.f-wx)      *vy1*vx0;
    float w11 = wy*wx            *vy1*vx1;
    int i00 = y0c*64+x0c, i01 = y0c*64+x1c, i10 = y1c*64+x0c, i11 = y1c*64+x1c;
    const float* sb = skipu + (size_t)b * SKIPCH * NPIX;
    #pragma unroll 4
    for (int ic = 0; ic < 64; ic++) {
        const float* pc = sb + ic * NPIX;
        float v = w00*pc[i00] + w01*pc[i01] + w10*pc[i10] + w11*pc[i11];
        col[(((size_t)(b*64 + ic))*9 + k) * NPIX + p] = v;
    }
}

// ---------------- tensor-core 1x1-conv GEMM (tf32 3-pass) ----------------
// out[b,o,n] = act(sum_k in[b,k,n]*w[o,k]+bias) (+res)
// Block: 32 outputs x 128 pixels, 128 threads (4 warps).
__global__ void __launch_bounds__(128) k_gemm_tc(
    const float* __restrict__ inA, const float* __restrict__ inB, int K, int K1,
    const float* __restrict__ w, const float* __restrict__ bias,
    const float* __restrict__ res, int act,
    float* __restrict__ out, int O)
{
    __shared__ float sWh[32][36];
    __shared__ float sWl[32][36];
    __shared__ __align__(16) float sIh[32][132];
    __shared__ __align__(16) float sIl[32][132];

    int b  = blockIdx.z;
    int o0 = blockIdx.y * 32;
    int n0 = blockIdx.x * 128;
    int t  = threadIdx.x;
    int warp = t >> 5, lane = t & 31;
    int gr = lane >> 2, tig = lane & 3;
    int wo = (warp & 1) * 16;
    int wn = (warp >> 1) * 64;
    int KB = K - K1;

    // staging indices
    int srow = t >> 2;          // 0..31 (k-row for I, o-row for W)
    int snc  = (t & 3) * 32;    // n chunk for I
    int skc  = (t & 3) * 8;     // k chunk for W

    float c[8][4] = {};

    for (int k0 = 0; k0 < K; k0 += 32) {
        __syncthreads();
        // --- stage W tile [32 o][32 k], split hi/lo ---
        {
            const float* wp = w + (size_t)(o0 + srow) * K + k0 + skc;
            #pragma unroll
            for (int j = 0; j < 8; j++) {
                float v = wp[j];
                float hi = tf32f(v);
                sWh[srow][skc + j] = hi;
                sWl[srow][skc + j] = tf32f(v - hi);
            }
        }
        // --- stage I tile [32 k][128 n], split hi/lo, float4 stores ---
        {
            int k = k0 + srow;
            const float* src = (k < K1)
                ? (inA + ((size_t)b*K1 + k) * NPIX)
                : (inB + ((size_t)b*KB + (k - K1)) * NPIX);
            #pragma unroll
            for (int j = 0; j < 8; j++) {
                float4 v = *(const float4*)(src + n0 + snc + j*4);
                float4 h, l;
                h.x = tf32f(v.x); l.x = tf32f(v.x - h.x);
                h.y = tf32f(v.y); l.y = tf32f(v.y - h.y);
                h.z = tf32f(v.z); l.z = tf32f(v.z - h.z);
                h.w = tf32f(v.w); l.w = tf32f(v.w - h.w);
                *(float4*)&sIh[srow][snc + j*4] = h;
                *(float4*)&sIl[srow][snc + j*4] = l;
            }
        }
        __syncthreads();

        #pragma unroll
        for (int ks = 0; ks < 4; ks++) {
            int kb = ks * 8;
            float ah[4], al[4];
            ah[0] = sWh[wo+gr  ][kb+tig];   ah[1] = sWh[wo+gr+8][kb+tig];
            ah[2] = sWh[wo+gr  ][kb+tig+4]; ah[3] = sWh[wo+gr+8][kb+tig+4];
            al[0] = sWl[wo+gr  ][kb+tig];   al[1] = sWl[wo+gr+8][kb+tig];
            al[2] = sWl[wo+gr  ][kb+tig+4]; al[3] = sWl[wo+gr+8][kb+tig+4];
            #pragma unroll
            for (int nt = 0; nt < 8; nt++) {
                int ncol = wn + nt*8 + gr;
                float bh0 = sIh[kb+tig  ][ncol];
                float bh1 = sIh[kb+tig+4][ncol];
                float bl0 = sIl[kb+tig  ][ncol];
                float bl1 = sIl[kb+tig+4][ncol];
                mma_tf32(c[nt], ah, bh0, bh1);
                mma_tf32(c[nt], ah, bl0, bl1);
                mma_tf32(c[nt], al, bh0, bh1);
            }
        }
    }

    // --- epilogue ---
    int or0 = o0 + wo + gr;
    int or1 = or0 + 8;
    float bv0 = bias ? bias[or0] : 0.f;
    float bv1 = bias ? bias[or1] : 0.f;
    size_t base0 = ((size_t)b*O + or0) * NPIX + n0 + wn;
    size_t base1 = ((size_t)b*O + or1) * NPIX + n0 + wn;
    #pragma unroll
    for (int nt = 0; nt < 8; nt++) {
        int nc = nt*8 + 2*tig;
        float v0 = c[nt][0] + bv0, v1 = c[nt][1] + bv0;
        float v2 = c[nt][2] + bv1, v3 = c[nt][3] + bv1;
        if (act == 1) {
            v0 = gelu_f(v0); v1 = gelu_f(v1);
            v2 = gelu_f(v2); v3 = gelu_f(v3);
        }
        if (res) {
            v0 += res[base0 + nc]; v1 += res[base0 + nc + 1];
            v2 += res[base1 + nc]; v3 += res[base1 + nc + 1];
        }
        float2 a = {v0, v1}, bb = {v2, v3};
        *(float2*)(out + base0 + nc) = a;
        *(float2*)(out + base1 + nc) = bb;
    }
}

// ---------------- tensor-core attention: N=4096, c=32, tf32 MMA ----------------
__global__ void __launch_bounds__(128) k_attn_tc(const float* __restrict__ qkv,
                                                 float* __restrict__ av)
{
    __shared__ float sQh[64][36];   // [query][c]
    __shared__ float sQl[64][36];
    __shared__ float sKh[32][36];   // [key][c]
    __shared__ float sKl[32][36];
    __shared__ float sV [32][36];   // [c][key]
    __shared__ float sP [64][36];   // [query][key] / output transpose

    int b    = blockIdx.y;
    int n0   = blockIdx.x * 64;
    int t    = threadIdx.x;
    int warp = t >> 5, lane = t & 31;
    int gr   = lane >> 2;     // 0..7
    int tig  = lane & 3;      // 0..3
    int wrow = warp * 16;

    const float* qb = qkv + (size_t)b * 96 * NPIX;
    const float* kb = qb + 32 * NPIX;
    const float* vb = qb + 64 * NPIX;

    #pragma unroll
    for (int i = 0; i < 16; i++) {
        int flat = i * 128 + t;
        int c = flat >> 6, j = flat & 63;
        float v = qb[c*NPIX + n0 + j] * 0.17677669529663687f;
        float hi = tf32f(v);
        sQh[j][c] = hi;
        sQl[j][c] = tf32f(v - hi);
    }

    float o[4][4] = {};
    float l0 = 0.f, l1 = 0.f;

    for (int t0 = 0; t0 < NPIX; t0 += 32) {
        __syncthreads();
        #pragma unroll
        for (int i = 0; i < 8; i++) {
            int c = i * 4 + warp;
            float kv = kb[c*NPIX + t0 + lane];
            float hi = tf32f(kv);
            sKh[lane][c] = hi;
            sKl[lane][c] = tf32f(kv - hi);
            sV[c][lane]  = tf32f(vb[c*NPIX + t0 + lane]);
        }
        __syncthreads();

        float s[4][4] = {};
        #pragma unroll
        for (int k0 = 0; k0 < 32; k0 += 8) {
            float ah[4], al[4];
            ah[0] = sQh[wrow+gr  ][k0+tig];   ah[1] = sQh[wrow+gr+8][k0+tig];
            ah[2] = sQh[wrow+gr  ][k0+tig+4]; ah[3] = sQh[wrow+gr+8][k0+tig+4];
            al[0] = sQl[wrow+gr  ][k0+tig];   al[1] = sQl[wrow+gr+8][k0+tig];
            al[2] = sQl[wrow+gr  ][k0+tig+4]; al[3] = sQl[wrow+gr+8][k0+tig+4];
            #pragma unroll
            for (int nt = 0; nt < 4; nt++) {
                float bh0 = sKh[nt*8+gr][k0+tig], bh1 = sKh[nt*8+gr][k0+tig+4];
                float bl0 = sKl[nt*8+gr][k0+tig], bl1 = sKl[nt*8+gr][k0+tig+4];
                mma_tf32(s[nt], ah, bh0, bh1);
                mma_tf32(s[nt], ah, bl0, bl1);
                mma_tf32(s[nt], al, bh0, bh1);
            }
        }

        #pragma unroll
        for (int nt = 0; nt < 4; nt++) {
            float p0 = __expf(s[nt][0]);
            float p1 = __expf(s[nt][1]);
            float p2 = __expf(s[nt][2]);
            float p3 = __expf(s[nt][3]);
            l0 += p0 + p1;
            l1 += p2 + p3;
            sP[wrow+gr  ][nt*8 + 2*tig    ] = tf32f(p0);
            sP[wrow+gr  ][nt*8 + 2*tig + 1] = tf32f(p1);
            sP[wrow+gr+8][nt*8 + 2*tig    ] = tf32f(p2);
            sP[wrow+gr+8][nt*8 + 2*tig + 1] = tf32f(p3);
        }
        __syncwarp();

        #pragma unroll
        for (int k0 = 0; k0 < 32; k0 += 8) {
            float a[4];
            a[0] = sP[wrow+gr  ][k0+tig];   a[1] = sP[wrow+gr+8][k0+tig];
            a[2] = sP[wrow+gr  ][k0+tig+4]; a[3] = sP[wrow+gr+8][k0+tig+4];
            #pragma unroll
            for (int ct = 0; ct < 4; ct++) {
                float b0 = sV[ct*8+gr][k0+tig];
                float b1 = sV[ct*8+gr][k0+tig+4];
                mma_tf32(o[ct], a, b0, b1);
            }
        }
    }

    l0 += __shfl_xor_sync(0xffffffffu, l0, 1);
    l0 += __shfl_xor_sync(0xffffffffu, l0, 2);
    l1 += __shfl_xor_sync(0xffffffffu, l1, 1);
    l1 += __shfl_xor_sync(0xffffffffu, l1, 2);
    float inv0 = 1.f / l0, inv1 = 1.f / l1;

    __syncthreads();
    #pragma unroll
    for (int ct = 0; ct < 4; ct++) {
        sP[wrow+gr  ][ct*8 + 2*tig    ] = o[ct][0] * inv0;
        sP[wrow+gr  ][ct*8 + 2*tig + 1] = o[ct][1] * inv0;
        sP[wrow+gr+8][ct*8 + 2*tig    ] = o[ct][2] * inv1;
        sP[wrow+gr+8][ct*8 + 2*tig + 1] = o[ct][3] * inv1;
    }
    __syncthreads();

    #pragma unroll
    for (int i = 0; i < 16; i++) {
        int flat = i * 128 + t;
        int c = flat >> 6, j = flat & 63;
        av[((size_t)b*32 + c)*NPIX + n0 + j] = sP[j][c];
    }
}

// ---------------- LayerNorm over 64 channels ----------------
__global__ void k_ln(const float* __restrict__ e, const float* __restrict__ g,
                     const float* __restrict__ bta, float* __restrict__ outp)
{
    int idx = blockIdx.x * blockDim.x + threadIdx.x;
    if (idx >= BATCH * NPIX) return;
    int b = idx >> 12, p = idx & 4095;
    float vals[64];
    float s = 0.f, s2 = 0.f;
    #pragma unroll
    for (int c = 0; c < 64; c++) {
        float v = e[(((size_t)b*64 + c) << 12) + p];
        vals[c] = v; s += v; s2 += v*v;
    }
    float mu = s * (1.f/64.f);
    float var = s2 * (1.f/64.f) - mu*mu;
    float rstd = rsqrtf(var + 1e-5f);
    #pragma unroll
    for (int c = 0; c < 64; c++)
        outp[(((size_t)b*64 + c) << 12) + p] = (vals[c] - mu)*rstd*g[c] + bta[c];
}

// ---------------- depthwise 3x3 + gelu ----------------
__global__ void k_dw(const float* __restrict__ h1, const float* __restrict__ w,
                     const float* __restrict__ bias, float* __restrict__ h2)
{
    int idx = blockIdx.x * blockDim.x + threadIdx.x;
    if (idx >= BATCH * 256 * NPIX) return;
    int p = idx & 4095, c = (idx >> 12) & 255;
    int y = p >> 6, x = p & 63;
    const float* src = h1 + ((size_t)idx - p);
    const float* wc = w + c * 9;
    float acc = bias[c];
    #pragma unroll
    for (int dy = -1; dy <= 1; dy++)
        #pragma unroll
        for (int dx = -1; dx <= 1; dx++) {
            int yy = y + dy, xx = x + dx;
            if ((unsigned)yy < 64u && (unsigned)xx < 64u)
                acc += src[yy*64 + xx] * wc[(dy+1)*3 + (dx+1)];
        }
    h2[idx] = gelu_f(acc);
}

// ---------------- host ----------------
extern "C" void kernel_launch(void* const* d_in, const int* in_sizes, int n_in,
                              void* d_out, int out_size)
{
    const float* x        = (const float*)d_in[0];
    const float* skip     = (const float*)d_in[1];
    const float* qkv_w    = (const float*)d_in[2];
    const float* qkv_b    = (const float*)d_in[3];
    const float* proj_w   = (const float*)d_in[4];
    const float* proj_b   = (const float*)d_in[5];
    const float* edge_w   = (const float*)d_in[6];
    const float* thick_w  = (const float*)d_in[7];
    const float* thick_b  = (const float*)d_in[8];
    const float* off_w    = (const float*)d_in[9];
    const float* off_b    = (const float*)d_in[10];
    const float* deform_w = (const float*)d_in[11];
    const float* deform_b = (const float*)d_in[12];
    const float* ln_g     = (const float*)d_in[13];
    const float* ln_b     = (const float*)d_in[14];
    const float* mlp1_w   = (const float*)d_in[15];
    const float* mlp1_b   = (const float*)d_in[16];
    const float* dw_w     = (const float*)d_in[17];
    const float* dw_b     = (const float*)d_in[18];
    const float* mlp2_w   = (const float*)d_in[19];
    const float* mlp2_b   = (const float*)d_in[20];
    const float* down_w   = (const float*)d_in[21];
    const float* down_b   = (const float*)d_in[22];
    const float* up_w     = (const float*)d_in[23];
    const float* up_b     = (const float*)d_in[24];
    float* out = (float*)d_out;

    float *skipu, *meanv, *thick, *qkv, *avb, *x2, *edge, *col, *off, *offw, *offb;
    float *dd, *e, *ln, *h1, *h2, *tt;
    cudaGetSymbolAddress((void**)&skipu, g_skipu);
    cudaGetSymbolAddress((void**)&meanv, g_mean);
    cudaGetSymbolAddress((void**)&thick, g_thick);
    cudaGetSymbolAddress((void**)&qkv,   g_qkv);
    cudaGetSymbolAddress((void**)&avb,   g_av);
    cudaGetSymbolAddress((void**)&x2,    g_x2);
    cudaGetSymbolAddress((void**)&edge,  g_edge);
    cudaGetSymbolAddress((void**)&col,   g_col);
    cudaGetSymbolAddress((void**)&off,   g_off);
    cudaGetSymbolAddress((void**)&offw,  g_offw);
    cudaGetSymbolAddress((void**)&offb,  g_offb);
    cudaGetSymbolAddress((void**)&dd,    g_d);
    cudaGetSymbolAddress((void**)&e,     g_e);
    cudaGetSymbolAddress((void**)&ln,    g_ln);
    cudaGetSymbolAddress((void**)&h1,    g_h1);
    cudaGetSymbolAddress((void**)&h2,    g_h2);
    cudaGetSymbolAddress((void**)&tt,    g_t);

    // attention branch
    k_gemm_tc<<<dim3(32, 3, 4), 128>>>(x, nullptr, 256, 256, qkv_w, qkv_b, nullptr, 0, qkv, 96);
    k_attn_tc<<<dim3(64, 4), 128>>>(qkv, avb);
    k_gemm_tc<<<dim3(32, 8, 4), 128>>>(avb, nullptr, 32, 32, proj_w, proj_b, x, 0, x2, 256);

    // skip branch
    k_upsample<<<(BATCH*NPIX + 255)/256, 256>>>(skip, thick_w, thick_b, skipu, meanv, thick);
    k_edge<<<(BATCH*SKIPCH*NPIX + 255)/256, 256>>>(meanv, edge_w, edge);
    k_im2col<<<(BATCH*576*NPIX + 255)/256, 256>>>(edge, col);
    k_prep_offw<<<(32*576 + 255)/256, 256>>>(off_w, off_b, offw, offb);
    k_gemm_tc<<<dim3(32, 1, 4), 128>>>(col, nullptr, 576, 576, offw, offb, nullptr, 0, off, 32);
    k_sample<<<(BATCH*9*NPIX + 255)/256, 256>>>(off, thick, skipu, col);
    k_gemm_tc<<<dim3(32, 2, 4), 128>>>(col, nullptr, 576, 576, deform_w, deform_b, edge, 0, dd, 64);

    // merge + token mixer
    k_gemm_tc<<<dim3(32, 2, 4), 128>>>(x2, dd, 320, 256, down_w, down_b, nullptr, 0, e, 64);
    k_ln<<<(BATCH*NPIX + 255)/256, 256>>>(e, ln_g, ln_b, ln);
    k_gemm_tc<<<dim3(32, 8, 4), 128>>>(ln, nullptr, 64, 64, mlp1_w, mlp1_b, nullptr, 1, h1, 256);
    k_dw<<<(BATCH*256*NPIX + 255)/256, 256>>>(h1, dw_w, dw_b, h2);
    k_gemm_tc<<<dim3(32, 2, 4), 128>>>(h2, nullptr, 256, 256, mlp2_w, mlp2_b, e, 0, tt, 64);
    k_gemm_tc<<<dim3(32, 8, 4), 128>>>(tt, nullptr, 64, 64, up_w, up_b, nullptr, 0, out, 256);
}

// round 8
// speedup vs baseline: 1.0390x; 1.0390x over previous
#include <cuda_runtime.h>
#include <math.h>

#define BATCH 4
#define INCH 256
#define SKIPCH 64
#define EMBEDC 64
#define NPIX 4096   // 64*64

// ---------------- scratch (static device globals; no allocation) ----------------
__device__ float g_skipu[BATCH*SKIPCH*NPIX];
__device__ float g_mean [BATCH*NPIX];
__device__ float g_thick[BATCH*NPIX];
__device__ float g_qkv  [BATCH*96*NPIX];
__device__ float g_av   [BATCH*32*NPIX];
__device__ float g_x2   [BATCH*INCH*NPIX];
__device__ float g_edge [BATCH*SKIPCH*NPIX];
__device__ float g_col  [BATCH*576*NPIX];   // im2col(edge), then reused for sampled vals
__device__ float g_off  [BATCH*32*NPIX];    // 18 used, padded to 32
__device__ float g_offw [32*576];
__device__ float g_offb [32];
__device__ float g_d    [BATCH*SKIPCH*NPIX];
__device__ float g_e    [BATCH*EMBEDC*NPIX];
__device__ float g_ln   [BATCH*EMBEDC*NPIX];
__device__ float g_h1   [BATCH*256*NPIX];
__device__ float g_h2   [BATCH*256*NPIX];
__device__ float g_t    [BATCH*EMBEDC*NPIX];

__device__ __forceinline__ float gelu_f(float v) {
    return 0.5f * v * (1.0f + erff(v * 0.70710678118654752f));
}

__device__ __forceinline__ float tf32f(float x) {
    unsigned u;
    asm("cvt.rna.tf32.f32 %0, %1;" : "=r"(u) : "f"(x));
    return __uint_as_float(u);
}

// array-operand form (attention kernel; known-good there)
__device__ __forceinline__ void mma_tf32(float* d, const float* a, float b0, float b1) {
    asm volatile("mma.sync.aligned.m16n8k8.row.col.f32.tf32.tf32.f32 "
        "{%0,%1,%2,%3}, {%4,%5,%6,%7}, {%8,%9}, {%0,%1,%2,%3};"
        : "+f"(d[0]), "+f"(d[1]), "+f"(d[2]), "+f"(d[3])
        : "r"(__float_as_uint(a[0])), "r"(__float_as_uint(a[1])),
          "r"(__float_as_uint(a[2])), "r"(__float_as_uint(a[3])),
          "r"(__float_as_uint(b0)), "r"(__float_as_uint(b1)));
}

// scalar/float4 form (GEMM kernel; guarantees register accumulators)
__device__ __forceinline__ void mma_tf32v(float4& d,
                                          float a0, float a1, float a2, float a3,
                                          float b0, float b1) {
    asm volatile("mma.sync.aligned.m16n8k8.row.col.f32.tf32.tf32.f32 "
        "{%0,%1,%2,%3}, {%4,%5,%6,%7}, {%8,%9}, {%0,%1,%2,%3};"
        : "+f"(d.x), "+f"(d.y), "+f"(d.z), "+f"(d.w)
        : "r"(__float_as_uint(a0)), "r"(__float_as_uint(a1)),
          "r"(__float_as_uint(a2)), "r"(__float_as_uint(a3)),
          "r"(__float_as_uint(b0)), "r"(__float_as_uint(b1)));
}

// ---------------- bilinear upsample (half-pixel, clamp) + channel mean + thick ----------------
__global__ void k_upsample(const float* __restrict__ skip, const float* __restrict__ thick_w,
                           const float* __restrict__ thick_b,
                           float* __restrict__ skipu, float* __restrict__ meanv,
                           float* __restrict__ thick)
{
    int idx = blockIdx.x * blockDim.x + threadIdx.x;
    if (idx >= BATCH * NPIX) return;
    int b = idx >> 12, p = idx & 4095;
    int oy = p >> 6, ox = p & 63;
    float sy = oy * 0.5f - 0.25f, sx = ox * 0.5f - 0.25f;
    float y0f = floorf(sy), x0f = floorf(sx);
    float wy = sy - y0f, wx = sx - x0f;
    int y0 = (int)y0f, x0 = (int)x0f;
    int y0c = min(max(y0, 0), 31), y1c = min(max(y0 + 1, 0), 31);
    int x0c = min(max(x0, 0), 31), x1c = min(max(x0 + 1, 0), 31);
    float w00 = (1.f - wy) * (1.f - wx), w01 = (1.f - wy) * wx;
    float w10 = wy * (1.f - wx), w11 = wy * wx;
    const float* sb = skip + (size_t)b * SKIPCH * 1024;
    float s = 0.f, ta = 0.f;
    #pragma unroll 4
    for (int c = 0; c < SKIPCH; c++) {
        const float* pc = sb + c * 1024;
        float v = w00 * pc[y0c*32 + x0c] + w01 * pc[y0c*32 + x1c]
                + w10 * pc[y1c*32 + x0c] + w11 * pc[y1c*32 + x1c];
        skipu[((size_t)(b*SKIPCH + c)) * NPIX + p] = v;
        s += v;
        ta += v * thick_w[c];
    }
    meanv[idx] = s * (1.0f / 64.0f);
    thick[idx] = 1.0f / (1.0f + __expf(-(ta + thick_b[0])));
}

// ---------------- edge conv: 3x3, 1->64 ch, no bias, zero pad ----------------
__global__ void k_edge(const float* __restrict__ meanv, const float* __restrict__ edge_w,
                       float* __restrict__ edge)
{
    int idx = blockIdx.x * blockDim.x + threadIdx.x;
    if (idx >= BATCH * SKIPCH * NPIX) return;
    int p = idx & 4095, oc = (idx >> 12) & 63, b = idx >> 18;
    int y = p >> 6, x = p & 63;
    const float* mb = meanv + b * NPIX;
    const float* w = edge_w + oc * 9;
    float acc = 0.f;
    #pragma unroll
    for (int dy = -1; dy <= 1; dy++)
        #pragma unroll
        for (int dx = -1; dx <= 1; dx++) {
            int yy = y + dy, xx = x + dx;
            if ((unsigned)yy < 64u && (unsigned)xx < 64u)
                acc += mb[yy*64 + xx] * w[(dy+1)*3 + (dx+1)];
        }
    edge[idx] = acc;
}

// ---------------- im2col of edge: rows ic*9+tap ----------------
__global__ void k_im2col(const float* __restrict__ edge, float* __restrict__ col)
{
    int idx = blockIdx.x * blockDim.x + threadIdx.x;
    if (idx >= BATCH * 576 * NPIX) return;
    int p = idx & 4095;
    int r = (idx >> 12) % 576;
    int b = idx / (576 * NPIX);
    int ic = r / 9, tap = r % 9;
    int y = (p >> 6) + tap/3 - 1, x = (p & 63) + tap%3 - 1;
    float v = 0.f;
    if ((unsigned)y < 64u && (unsigned)x < 64u)
        v = edge[(((size_t)b*64 + ic) << 12) + y*64 + x];
    col[idx] = v;
}

// ---------------- pad off weights 18 -> 32 rows ----------------
__global__ void k_prep_offw(const float* __restrict__ off_w, const float* __restrict__ off_b,
                            float* __restrict__ wpad, float* __restrict__ bpad)
{
    int idx = blockIdx.x * blockDim.x + threadIdx.x;
    if (idx < 32 * 576) {
        int o = idx / 576, k = idx % 576;
        wpad[idx] = (o < 18) ? off_w[o*576 + k] : 0.f;
    }
    if (idx < 32) bpad[idx] = (idx < 18) ? off_b[idx] : 0.f;
}

// ---------------- deformable bilinear sampling (guide scale fused) ----------------
__global__ void k_sample(const float* __restrict__ off, const float* __restrict__ thick,
                         const float* __restrict__ skipu, float* __restrict__ col)
{
    int idx = blockIdx.x * blockDim.x + threadIdx.x;
    if (idx >= BATCH * 9 * NPIX) return;
    int p = idx & 4095;
    int k = (idx >> 12) % 9;
    int b = idx / (9 * NPIX);
    float guide = 1.f + 16.f * thick[b*NPIX + p];
    float dy = off[(((size_t)b*32 + 2*k    ) << 12) + p] * guide;
    float dx = off[(((size_t)b*32 + 2*k + 1) << 12) + p] * guide;
    float py = (float)(p >> 6) + (float)(k/3 - 1) + dy;
    float px = (float)(p & 63) + (float)(k%3 - 1) + dx;
    float y0f = floorf(py), x0f = floorf(px);
    float wy = py - y0f, wx = px - x0f;
    int y0 = (int)y0f, x0 = (int)x0f;
    int y1 = y0 + 1, x1 = x0 + 1;
    float vy0 = (y0 >= 0 && y0 < 64) ? 1.f : 0.f;
    float vy1 = (y1 >= 0 && y1 < 64) ? 1.f : 0.f;
    float vx0 = (x0 >= 0 && x0 < 64) ? 1.f : 0.f;
    float vx1 = (x1 >= 0 && x1 < 64) ? 1.f : 0.f;
    int y0c = min(max(y0,0),63), y1c = min(max(y1,0),63);
    int x0c = min(max(x0,0),63), x1c = min(max(x1,0),63);
    float w00 = (1.f-wy)*(1.f-wx)*vy0*vx0;
    float w01 = (1.f-wy)*wx      *vy0*vx1;
    float w10 = wy*(1.f-wx)      *vy1*vx0;
    float w11 = wy*wx            *vy1*vx1;
    int i00 = y0c*64+x0c, i01 = y0c*64+x1c, i10 = y1c*64+x0c, i11 = y1c*64+x1c;
    const float* sb = skipu + (size_t)b * SKIPCH * NPIX;
    #pragma unroll 4
    for (int ic = 0; ic < 64; ic++) {
        const float* pc = sb + ic * NPIX;
        float v = w00*pc[i00] + w01*pc[i01] + w10*pc[i10] + w11*pc[i11];
        col[(((size_t)(b*64 + ic))*9 + k) * NPIX + p] = v;
    }
}

// ---------------- tensor-core 1x1-conv GEMM v2 (tf32 3-pass, register accums) ----------------
// out[b,o,n] = act(sum_k in[b,k,n]*w[o,k]+bias) (+res)
// Block: 32 outputs x 128 pixels, 128 threads (4 warps).
// Accumulators: 8 explicit float4 (manually unrolled nt) -> guaranteed registers.
#define GEMM_NT(CC, NT) do {                                          \
    int ncol_ = wn + (NT)*8 + gr;                                     \
    float bh0_ = sIh[kb+tig  ][ncol_];                                \
    float bh1_ = sIh[kb+tig+4][ncol_];                                \
    float bl0_ = sIl[kb+tig  ][ncol_];                                \
    float bl1_ = sIl[kb+tig+4][ncol_];                                \
    mma_tf32v(CC, ah0, ah1, ah2, ah3, bh0_, bh1_);                    \
    mma_tf32v(CC, ah0, ah1, ah2, ah3, bl0_, bl1_);                    \
    mma_tf32v(CC, al0, al1, al2, al3, bh0_, bh1_);                    \
} while (0)

#define GEMM_EPI(CC, NT) do {                                         \
    int nc_ = (NT)*8 + 2*tig;                                         \
    float v0_ = CC.x + bv0, v1_ = CC.y + bv0;                         \
    float v2_ = CC.z + bv1, v3_ = CC.w + bv1;                         \
    if (act == 1) {                                                   \
        v0_ = gelu_f(v0_); v1_ = gelu_f(v1_);                         \
        v2_ = gelu_f(v2_); v3_ = gelu_f(v3_);                         \
    }                                                                 \
    if (res) {                                                        \
        v0_ += res[base0 + nc_]; v1_ += res[base0 + nc_ + 1];         \
        v2_ += res[base1 + nc_]; v3_ += res[base1 + nc_ + 1];         \
    }                                                                 \
    *(float2*)(out + base0 + nc_) = make_float2(v0_, v1_);            \
    *(float2*)(out + base1 + nc_) = make_float2(v2_, v3_);            \
} while (0)

__global__ void __launch_bounds__(128) k_gemm_tc(
    const float* __restrict__ inA, const float* __restrict__ inB, int K, int K1,
    const float* __restrict__ w, const float* __restrict__ bias,
    const float* __restrict__ res, int act,
    float* __restrict__ out, int O)
{
    __shared__ float sWh[32][36];
    __shared__ float sWl[32][36];
    __shared__ __align__(16) float sIh[32][136];   // stride 136: conflict-free B-frag reads
    __shared__ __align__(16) float sIl[32][136];

    int b  = blockIdx.z;
    int o0 = blockIdx.y * 32;
    int n0 = blockIdx.x * 128;
    int t  = threadIdx.x;
    int warp = t >> 5, lane = t & 31;
    int gr = lane >> 2, tig = lane & 3;
    int wo = (warp & 1) * 16;
    int wn = (warp >> 1) * 64;
    int KB = K - K1;

    // staging indices
    int srow = t >> 2;          // 0..31 (k-row for I, o-row for W)
    int snc  = (t & 3) * 32;    // n chunk for I
    int skc  = (t & 3) * 8;     // k chunk for W

    float4 c0 = {0.f,0.f,0.f,0.f}, c1 = c0, c2 = c0, c3 = c0;
    float4 c4 = c0, c5 = c0, c6 = c0, c7 = c0;

    for (int k0 = 0; k0 < K; k0 += 32) {
        __syncthreads();
        // --- stage W tile [32 o][32 k], split hi/lo ---
        {
            const float* wp = w + (size_t)(o0 + srow) * K + k0 + skc;
            #pragma unroll
            for (int j = 0; j < 8; j++) {
                float v = wp[j];
                float hi = tf32f(v);
                sWh[srow][skc + j] = hi;
                sWl[srow][skc + j] = tf32f(v - hi);
            }
        }
        // --- stage I tile [32 k][128 n], split hi/lo, float4 stores ---
        {
            int k = k0 + srow;
            const float* src = (k < K1)
                ? (inA + ((size_t)b*K1 + k) * NPIX)
                : (inB + ((size_t)b*KB + (k - K1)) * NPIX);
            #pragma unroll
            for (int j = 0; j < 8; j++) {
                float4 v = *(const float4*)(src + n0 + snc + j*4);
                float4 h, l;
                h.x = tf32f(v.x); l.x = tf32f(v.x - h.x);
                h.y = tf32f(v.y); l.y = tf32f(v.y - h.y);
                h.z = tf32f(v.z); l.z = tf32f(v.z - h.z);
                h.w = tf32f(v.w); l.w = tf32f(v.w - h.w);
                *(float4*)&sIh[srow][snc + j*4] = h;
                *(float4*)&sIl[srow][snc + j*4] = l;
            }
        }
        __syncthreads();

        #pragma unroll
        for (int ks = 0; ks < 4; ks++) {
            int kb = ks * 8;
            float ah0 = sWh[wo+gr  ][kb+tig];
            float ah1 = sWh[wo+gr+8][kb+tig];
            float ah2 = sWh[wo+gr  ][kb+tig+4];
            float ah3 = sWh[wo+gr+8][kb+tig+4];
            float al0 = sWl[wo+gr  ][kb+tig];
            float al1 = sWl[wo+gr+8][kb+tig];
            float al2 = sWl[wo+gr  ][kb+tig+4];
            float al3 = sWl[wo+gr+8][kb+tig+4];
            GEMM_NT(c0, 0); GEMM_NT(c1, 1); GEMM_NT(c2, 2); GEMM_NT(c3, 3);
            GEMM_NT(c4, 4); GEMM_NT(c5, 5); GEMM_NT(c6, 6); GEMM_NT(c7, 7);
        }
    }

    // --- epilogue ---
    int or0 = o0 + wo + gr;
    int or1 = or0 + 8;
    float bv0 = bias ? bias[or0] : 0.f;
    float bv1 = bias ? bias[or1] : 0.f;
    size_t base0 = ((size_t)b*O + or0) * NPIX + n0 + wn;
    size_t base1 = ((size_t)b*O + or1) * NPIX + n0 + wn;
    GEMM_EPI(c0, 0); GEMM_EPI(c1, 1); GEMM_EPI(c2, 2); GEMM_EPI(c3, 3);
    GEMM_EPI(c4, 4); GEMM_EPI(c5, 5); GEMM_EPI(c6, 6); GEMM_EPI(c7, 7);
}

// ---------------- tensor-core attention: N=4096, c=32, tf32 MMA ----------------
__global__ void __launch_bounds__(128) k_attn_tc(const float* __restrict__ qkv,
                                                 float* __restrict__ av)
{
    __shared__ float sQh[64][36];   // [query][c]
    __shared__ float sQl[64][36];
    __shared__ float sKh[32][36];   // [key][c]
    __shared__ float sKl[32][36];
    __shared__ float sV [32][36];   // [c][key]
    __shared__ float sP [64][36];   // [query][key] / output transpose

    int b    = blockIdx.y;
    int n0   = blockIdx.x * 64;
    int t    = threadIdx.x;
    int warp = t >> 5, lane = t & 31;
    int gr   = lane >> 2;     // 0..7
    int tig  = lane & 3;      // 0..3
    int wrow = warp * 16;

    const float* qb = qkv + (size_t)b * 96 * NPIX;
    const float* kb = qb + 32 * NPIX;
    const float* vb = qb + 64 * NPIX;

    #pragma unroll
    for (int i = 0; i < 16; i++) {
        int flat = i * 128 + t;
        int c = flat >> 6, j = flat & 63;
        float v = qb[c*NPIX + n0 + j] * 0.17677669529663687f;
        float hi = tf32f(v);
        sQh[j][c] = hi;
        sQl[j][c] = tf32f(v - hi);
    }

    float o[4][4] = {};
    float l0 = 0.f, l1 = 0.f;

    for (int t0 = 0; t0 < NPIX; t0 += 32) {
        __syncthreads();
        #pragma unroll
        for (int i = 0; i < 8; i++) {
            int c = i * 4 + warp;
            float kv = kb[c*NPIX + t0 + lane];
            float hi = tf32f(kv);
            sKh[lane][c] = hi;
            sKl[lane][c] = tf32f(kv - hi);
            sV[c][lane]  = tf32f(vb[c*NPIX + t0 + lane]);
        }
        __syncthreads();

        float s[4][4] = {};
        #pragma unroll
        for (int k0 = 0; k0 < 32; k0 += 8) {
            float ah[4], al[4];
            ah[0] = sQh[wrow+gr  ][k0+tig];   ah[1] = sQh[wrow+gr+8][k0+tig];
            ah[2] = sQh[wrow+gr  ][k0+tig+4]; ah[3] = sQh[wrow+gr+8][k0+tig+4];
            al[0] = sQl[wrow+gr  ][k0+tig];   al[1] = sQl[wrow+gr+8][k0+tig];
            al[2] = sQl[wrow+gr  ][k0+tig+4]; al[3] = sQl[wrow+gr+8][k0+tig+4];
            #pragma unroll
            for (int nt = 0; nt < 4; nt++) {
                float bh0 = sKh[nt*8+gr][k0+tig], bh1 = sKh[nt*8+gr][k0+tig+4];
                float bl0 = sKl[nt*8+gr][k0+tig], bl1 = sKl[nt*8+gr][k0+tig+4];
                mma_tf32(s[nt], ah, bh0, bh1);
                mma_tf32(s[nt], ah, bl0, bl1);
                mma_tf32(s[nt], al, bh0, bh1);
            }
        }

        #pragma unroll
        for (int nt = 0; nt < 4; nt++) {
            float p0 = __expf(s[nt][0]);
            float p1 = __expf(s[nt][1]);
            float p2 = __expf(s[nt][2]);
            float p3 = __expf(s[nt][3]);
            l0 += p0 + p1;
            l1 += p2 + p3;
            sP[wrow+gr  ][nt*8 + 2*tig    ] = tf32f(p0);
            sP[wrow+gr  ][nt*8 + 2*tig + 1] = tf32f(p1);
            sP[wrow+gr+8][nt*8 + 2*tig    ] = tf32f(p2);
            sP[wrow+gr+8][nt*8 + 2*tig + 1] = tf32f(p3);
        }
        __syncwarp();

        #pragma unroll
        for (int k0 = 0; k0 < 32; k0 += 8) {
            float a[4];
            a[0] = sP[wrow+gr  ][k0+tig];   a[1] = sP[wrow+gr+8][k0+tig];
            a[2] = sP[wrow+gr  ][k0+tig+4]; a[3] = sP[wrow+gr+8][k0+tig+4];
            #pragma unroll
            for (int ct = 0; ct < 4; ct++) {
                float b0 = sV[ct*8+gr][k0+tig];
                float b1 = sV[ct*8+gr][k0+tig+4];
                mma_tf32(o[ct], a, b0, b1);
            }
        }
    }

    l0 += __shfl_xor_sync(0xffffffffu, l0, 1);
    l0 += __shfl_xor_sync(0xffffffffu, l0, 2);
    l1 += __shfl_xor_sync(0xffffffffu, l1, 1);
    l1 += __shfl_xor_sync(0xffffffffu, l1, 2);
    float inv0 = 1.f / l0, inv1 = 1.f / l1;

    __syncthreads();
    #pragma unroll
    for (int ct = 0; ct < 4; ct++) {
        sP[wrow+gr  ][ct*8 + 2*tig    ] = o[ct][0] * inv0;
        sP[wrow+gr  ][ct*8 + 2*tig + 1] = o[ct][1] * inv0;
        sP[wrow+gr+8][ct*8 + 2*tig    ] = o[ct][2] * inv1;
        sP[wrow+gr+8][ct*8 + 2*tig + 1] = o[ct][3] * inv1;
    }
    __syncthreads();

    #pragma unroll
    for (int i = 0; i < 16; i++) {
        int flat = i * 128 + t;
        int c = flat >> 6, j = flat & 63;
        av[((size_t)b*32 + c)*NPIX + n0 + j] = sP[j][c];
    }
}

// ---------------- LayerNorm over 64 channels ----------------
__global__ void k_ln(const float* __restrict__ e, const float* __restrict__ g,
                     const float* __restrict__ bta, float* __restrict__ outp)
{
    int idx = blockIdx.x * blockDim.x + threadIdx.x;
    if (idx >= BATCH * NPIX) return;
    int b = idx >> 12, p = idx & 4095;
    float vals[64];
    float s = 0.f, s2 = 0.f;
    #pragma unroll
    for (int c = 0; c < 64; c++) {
        float v = e[(((size_t)b*64 + c) << 12) + p];
        vals[c] = v; s += v; s2 += v*v;
    }
    float mu = s * (1.f/64.f);
    float var = s2 * (1.f/64.f) - mu*mu;
    float rstd = rsqrtf(var + 1e-5f);
    #pragma unroll
    for (int c = 0; c < 64; c++)
        outp[(((size_t)b*64 + c) << 12) + p] = (vals[c] - mu)*rstd*g[c] + bta[c];
}

// ---------------- depthwise 3x3 + gelu ----------------
__global__ void k_dw(const float* __restrict__ h1, const float* __restrict__ w,
                     const float* __restrict__ bias, float* __restrict__ h2)
{
    int idx = blockIdx.x * blockDim.x + threadIdx.x;
    if (idx >= BATCH * 256 * NPIX) return;
    int p = idx & 4095, c = (idx >> 12) & 255;
    int y = p >> 6, x = p & 63;
    const float* src = h1 + ((size_t)idx - p);
    const float* wc = w + c * 9;
    float acc = bias[c];
    #pragma unroll
    for (int dy = -1; dy <= 1; dy++)
        #pragma unroll
        for (int dx = -1; dx <= 1; dx++) {
            int yy = y + dy, xx = x + dx;
            if ((unsigned)yy < 64u && (unsigned)xx < 64u)
                acc += src[yy*64 + xx] * wc[(dy+1)*3 + (dx+1)];
        }
    h2[idx] = gelu_f(acc);
}

// ---------------- host ----------------
extern "C" void kernel_launch(void* const* d_in, const int* in_sizes, int n_in,
                              void* d_out, int out_size)
{
    const float* x        = (const float*)d_in[0];
    const float* skip     = (const float*)d_in[1];
    const float* qkv_w    = (const float*)d_in[2];
    const float* qkv_b    = (const float*)d_in[3];
    const float* proj_w   = (const float*)d_in[4];
    const float* proj_b   = (const float*)d_in[5];
    const float* edge_w   = (const float*)d_in[6];
    const float* thick_w  = (const float*)d_in[7];
    const float* thick_b  = (const float*)d_in[8];
    const float* off_w    = (const float*)d_in[9];
    const float* off_b    = (const float*)d_in[10];
    const float* deform_w = (const float*)d_in[11];
    const float* deform_b = (const float*)d_in[12];
    const float* ln_g     = (const float*)d_in[13];
    const float* ln_b     = (const float*)d_in[14];
    const float* mlp1_w   = (const float*)d_in[15];
    const float* mlp1_b   = (const float*)d_in[16];
    const float* dw_w     = (const float*)d_in[17];
    const float* dw_b     = (const float*)d_in[18];
    const float* mlp2_w   = (const float*)d_in[19];
    const float* mlp2_b   = (const float*)d_in[20];
    const float* down_w   = (const float*)d_in[21];
    const float* down_b   = (const float*)d_in[22];
    const float* up_w     = (const float*)d_in[23];
    const float* up_b     = (const float*)d_in[24];
    float* out = (float*)d_out;

    float *skipu, *meanv, *thick, *qkv, *avb, *x2, *edge, *col, *off, *offw, *offb;
    float *dd, *e, *ln, *h1, *h2, *tt;
    cudaGetSymbolAddress((void**)&skipu, g_skipu);
    cudaGetSymbolAddress((void**)&meanv, g_mean);
    cudaGetSymbolAddress((void**)&thick, g_thick);
    cudaGetSymbolAddress((void**)&qkv,   g_qkv);
    cudaGetSymbolAddress((void**)&avb,   g_av);
    cudaGetSymbolAddress((void**)&x2,    g_x2);
    cudaGetSymbolAddress((void**)&edge,  g_edge);
    cudaGetSymbolAddress((void**)&col,   g_col);
    cudaGetSymbolAddress((void**)&off,   g_off);
    cudaGetSymbolAddress((void**)&offw,  g_offw);
    cudaGetSymbolAddress((void**)&offb,  g_offb);
    cudaGetSymbolAddress((void**)&dd,    g_d);
    cudaGetSymbolAddress((void**)&e,     g_e);
    cudaGetSymbolAddress((void**)&ln,    g_ln);
    cudaGetSymbolAddress((void**)&h1,    g_h1);
    cudaGetSymbolAddress((void**)&h2,    g_h2);
    cudaGetSymbolAddress((void**)&tt,    g_t);

    // attention branch
    k_gemm_tc<<<dim3(32, 3, 4), 128>>>(x, nullptr, 256, 256, qkv_w, qkv_b, nullptr, 0, qkv, 96);
    k_attn_tc<<<dim3(64, 4), 128>>>(qkv, avb);
    k_gemm_tc<<<dim3(32, 8, 4), 128>>>(avb, nullptr, 32, 32, proj_w, proj_b, x, 0, x2, 256);

    // skip branch
    k_upsample<<<(BATCH*NPIX + 255)/256, 256>>>(skip, thick_w, thick_b, skipu, meanv, thick);
    k_edge<<<(BATCH*SKIPCH*NPIX + 255)/256, 256>>>(meanv, edge_w, edge);
    k_im2col<<<(BATCH*576*NPIX + 255)/256, 256>>>(edge, col);
    k_prep_offw<<<(32*576 + 255)/256, 256>>>(off_w, off_b, offw, offb);
    k_gemm_tc<<<dim3(32, 1, 4), 128>>>(col, nullptr, 576, 576, offw, offb, nullptr, 0, off, 32);
    k_sample<<<(BATCH*9*NPIX + 255)/256, 256>>>(off, thick, skipu, col);
    k_gemm_tc<<<dim3(32, 2, 4), 128>>>(col, nullptr, 576, 576, deform_w, deform_b, edge, 0, dd, 64);

    // merge + token mixer
    k_gemm_tc<<<dim3(32, 2, 4), 128>>>(x2, dd, 320, 256, down_w, down_b, nullptr, 0, e, 64);
    k_ln<<<(BATCH*NPIX + 255)/256, 256>>>(e, ln_g, ln_b, ln);
    k_gemm_tc<<<dim3(32, 8, 4), 128>>>(ln, nullptr, 64, 64, mlp1_w, mlp1_b, nullptr, 1, h1, 256);
    k_dw<<<(BATCH*256*NPIX + 255)/256, 256>>>(h1, dw_w, dw_b, h2);
    k_gemm_tc<<<dim3(32, 2, 4), 128>>>(h2, nullptr, 256, 256, mlp2_w, mlp2_b, e, 0, tt, 64);
    k_gemm_tc<<<dim3(32, 8, 4), 128>>>(tt, nullptr, 64, 64, up_w, up_b, nullptr, 0, out, 256);
}

// round 12
// speedup vs baseline: 1.3023x; 1.2534x over previous
#include <cuda_runtime.h>
#include <math.h>

#define BATCH 4
#define INCH 256
#define SKIPCH 64
#define EMBEDC 64
#define NPIX 4096   // 64*64

// ---------------- scratch (static device globals; no allocation) ----------------
__device__ float g_skipu[BATCH*SKIPCH*NPIX];
__device__ float g_mean [BATCH*NPIX];
__device__ float g_thick[BATCH*NPIX];
__device__ float g_qkv  [BATCH*96*NPIX];
__device__ float g_av   [BATCH*32*NPIX];
__device__ float g_x2   [BATCH*INCH*NPIX];
__device__ float g_edge [BATCH*SKIPCH*NPIX];
__device__ float g_col  [BATCH*576*NPIX];
__device__ float g_off  [BATCH*32*NPIX];
__device__ float g_offw [32*576];
__device__ float g_offb [32];
__device__ float g_d    [BATCH*SKIPCH*NPIX];
__device__ float g_e    [BATCH*EMBEDC*NPIX];
__device__ float g_ln   [BATCH*EMBEDC*NPIX];
__device__ float g_h1   [BATCH*256*NPIX];
__device__ float g_h2   [BATCH*256*NPIX];
__device__ float g_t    [BATCH*EMBEDC*NPIX];

__device__ __forceinline__ float gelu_f(float v) {
    return 0.5f * v * (1.0f + erff(v * 0.70710678118654752f));
}

__device__ __forceinline__ float tf32f(float x) {
    unsigned u;
    asm("cvt.rna.tf32.f32 %0, %1;" : "=r"(u) : "f"(x));
    return __uint_as_float(u);
}

__device__ __forceinline__ void mma_tf32(float* d, const float* a, float b0, float b1) {
    asm volatile("mma.sync.aligned.m16n8k8.row.col.f32.tf32.tf32.f32 "
        "{%0,%1,%2,%3}, {%4,%5,%6,%7}, {%8,%9}, {%0,%1,%2,%3};"
        : "+f"(d[0]), "+f"(d[1]), "+f"(d[2]), "+f"(d[3])
        : "r"(__float_as_uint(a[0])), "r"(__float_as_uint(a[1])),
          "r"(__float_as_uint(a[2])), "r"(__float_as_uint(a[3])),
          "r"(__float_as_uint(b0)), "r"(__float_as_uint(b1)));
}

// ---------------- upsample v2: 64 pixels x 4 channel-groups per block ----------------
__global__ void __launch_bounds__(256) k_upsample(
    const float* __restrict__ skip, const float* __restrict__ thick_w,
    const float* __restrict__ thick_b,
    float* __restrict__ skipu, float* __restrict__ meanv, float* __restrict__ thick)
{
    __shared__ float red_s[4][64];
    __shared__ float red_t[4][64];
    int t  = threadIdx.x;
    int b  = blockIdx.x >> 6;
    int p0 = (blockIdx.x & 63) * 64;
    int pl = t & 63;
    int q  = t >> 6;
    int p  = p0 + pl;
    int oy = p >> 6, ox = p & 63;
    float sy = oy * 0.5f - 0.25f, sx = ox * 0.5f - 0.25f;
    float y0f = floorf(sy), x0f = floorf(sx);
    float wy = sy - y0f, wx = sx - x0f;
    int y0 = (int)y0f, x0 = (int)x0f;
    int y0c = min(max(y0, 0), 31), y1c = min(max(y0 + 1, 0), 31);
    int x0c = min(max(x0, 0), 31), x1c = min(max(x0 + 1, 0), 31);
    float w00 = (1.f - wy) * (1.f - wx), w01 = (1.f - wy) * wx;
    float w10 = wy * (1.f - wx), w11 = wy * wx;
    int i00 = y0c*32 + x0c, i01 = y0c*32 + x1c;
    int i10 = y1c*32 + x0c, i11 = y1c*32 + x1c;
    const float* sb = skip + (size_t)b * SKIPCH * 1024;
    float s = 0.f, ta = 0.f;
    #pragma unroll 4
    for (int i = 0; i < 16; i++) {
        int c = q*16 + i;
        const float* pc = sb + c * 1024;
        float v = w00*pc[i00] + w01*pc[i01] + w10*pc[i10] + w11*pc[i11];
        skipu[((size_t)(b*SKIPCH + c)) * NPIX + p] = v;
        s += v;
        ta += v * thick_w[c];
    }
    red_s[q][pl] = s; red_t[q][pl] = ta;
    __syncthreads();
    if (t < 64) {
        float ss = red_s[0][t] + red_s[1][t] + red_s[2][t] + red_s[3][t];
        float tt = red_t[0][t] + red_t[1][t] + red_t[2][t] + red_t[3][t];
        meanv[b*NPIX + p0 + t] = ss * (1.0f / 64.0f);
        thick[b*NPIX + p0 + t] = 1.0f / (1.0f + __expf(-(tt + thick_b[0])));
    }
}

// ---------------- edge conv: 3x3, 1->64 ch, no bias, zero pad ----------------
__global__ void k_edge(const float* __restrict__ meanv, const float* __restrict__ edge_w,
                       float* __restrict__ edge)
{
    int idx = blockIdx.x * blockDim.x + threadIdx.x;
    if (idx >= BATCH * SKIPCH * NPIX) return;
    int p = idx & 4095, oc = (idx >> 12) & 63, b = idx >> 18;
    int y = p >> 6, x = p & 63;
    const float* mb = meanv + b * NPIX;
    const float* w = edge_w + oc * 9;
    float acc = 0.f;
    #pragma unroll
    for (int dy = -1; dy <= 1; dy++)
        #pragma unroll
        for (int dx = -1; dx <= 1; dx++) {
            int yy = y + dy, xx = x + dx;
            if ((unsigned)yy < 64u && (unsigned)xx < 64u)
                acc += mb[yy*64 + xx] * w[(dy+1)*3 + (dx+1)];
        }
    edge[idx] = acc;
}

// ---------------- im2col of edge ----------------
__global__ void k_im2col(const float* __restrict__ edge, float* __restrict__ col)
{
    int idx = blockIdx.x * blockDim.x + threadIdx.x;
    if (idx >= BATCH * 576 * NPIX) return;
    int p = idx & 4095;
    int r = (idx >> 12) % 576;
    int b = idx / (576 * NPIX);
    int ic = r / 9, tap = r % 9;
    int y = (p >> 6) + tap/3 - 1, x = (p & 63) + tap%3 - 1;
    float v = 0.f;
    if ((unsigned)y < 64u && (unsigned)x < 64u)
        v = edge[(((size_t)b*64 + ic) << 12) + y*64 + x];
    col[idx] = v;
}

// ---------------- pad off weights 18 -> 32 rows ----------------
__global__ void k_prep_offw(const float* __restrict__ off_w, const float* __restrict__ off_b,
                            float* __restrict__ wpad, float* __restrict__ bpad)
{
    int idx = blockIdx.x * blockDim.x + threadIdx.x;
    if (idx < 32 * 576) {
        int o = idx / 576, k = idx % 576;
        wpad[idx] = (o < 18) ? off_w[o*576 + k] : 0.f;
    }
    if (idx < 32) bpad[idx] = (idx < 18) ? off_b[idx] : 0.f;
}

// ---------------- sample v2: guide fused, 8-channel groups (8x parallelism) ----------------
__global__ void __launch_bounds__(256) k_sample(
    const float* __restrict__ off, const float* __restrict__ thick,
    const float* __restrict__ skipu, float* __restrict__ col)
{
    int idx = blockIdx.x * blockDim.x + threadIdx.x;
    if (idx >= BATCH * 9 * 8 * NPIX) return;
    int p    = idx & 4095;
    int rest = idx >> 12;
    int g8   = rest & 7;  rest >>= 3;
    int k    = rest % 9;
    int b    = rest / 9;
    float guide = 1.f + 16.f * thick[b*NPIX + p];
    float dy = off[(((size_t)b*32 + 2*k    ) << 12) + p] * guide;
    float dx = off[(((size_t)b*32 + 2*k + 1) << 12) + p] * guide;
    float py = (float)(p >> 6) + (float)(k/3 - 1) + dy;
    float px = (float)(p & 63) + (float)(k%3 - 1) + dx;
    float y0f = floorf(py), x0f = floorf(px);
    float wy = py - y0f, wx = px - x0f;
    int y0 = (int)y0f, x0 = (int)x0f;
    int y1 = y0 + 1, x1 = x0 + 1;
    float vy0 = (y0 >= 0 && y0 < 64) ? 1.f : 0.f;
    float vy1 = (y1 >= 0 && y1 < 64) ? 1.f : 0.f;
    float vx0 = (x0 >= 0 && x0 < 64) ? 1.f : 0.f;
    float vx1 = (x1 >= 0 && x1 < 64) ? 1.f : 0.f;
    int y0c = min(max(y0,0),63), y1c = min(max(y1,0),63);
    int x0c = min(max(x0,0),63), x1c = min(max(x1,0),63);
    float w00 = (1.f-wy)*(1.f-wx)*vy0*vx0;
    float w01 = (1.f-wy)*wx      *vy0*vx1;
    float w10 = wy*(1.f-wx)      *vy1*vx0;
    float w11 = wy*wx            *vy1*vx1;
    int i00 = y0c*64+x0c, i01 = y0c*64+x1c, i10 = y1c*64+x0c, i11 = y1c*64+x1c;
    const float* sb = skipu + (size_t)b * SKIPCH * NPIX;
    #pragma unroll
    for (int i = 0; i < 8; i++) {
        int ic = g8*8 + i;
        const float* pc = sb + ic * NPIX;
        float v = w00*pc[i00] + w01*pc[i01] + w10*pc[i10] + w11*pc[i11];
        col[(((size_t)(b*64 + ic))*9 + k) * NPIX + p] = v;
    }
}

// ---------------- generic 1x1-conv GEMM (FFMA, proven) ----------------
// tiles: 32 outputs x 128 positions, 256 threads, 4x4 micro-tile
__global__ void __launch_bounds__(256) k_gemm(
    const float* __restrict__ inA, const float* __restrict__ inB, int K, int K1,
    const float* __restrict__ w, const float* __restrict__ bias,
    const float* __restrict__ res, int act,
    float* __restrict__ out, int O)
{
    __shared__ __align__(16) float sh_in[32][128];
    __shared__ __align__(16) float sh_w[32][36];
    int b  = blockIdx.z;
    int o0 = blockIdx.y * 32;
    int n0 = blockIdx.x * 128;
    int t  = threadIdx.x;
    int tn = (t & 31) * 4;
    int to = (t >> 5) * 4;
    int kr = t >> 5;
    int kc = t & 31;
    int KB = K - K1;
    float acc[4][4] = {};
    for (int k0 = 0; k0 < K; k0 += 32) {
        #pragma unroll
        for (int i = 0; i < 4; i++) {
            int kk = kr + i*8;
            int k = k0 + kk;
            const float* src = (k < K1)
                ? (inA + ((size_t)b*K1 + k) * NPIX)
                : (inB + ((size_t)b*KB + (k - K1)) * NPIX);
            *(float4*)&sh_in[kk][tn] = *(const float4*)(src + n0 + tn);
        }
        #pragma unroll
        for (int i = 0; i < 4; i++) {
            int oo = kr + i*8;
            sh_w[kc][oo] = w[(size_t)(o0 + oo)*K + k0 + kc];
        }
        __syncthreads();
        #pragma unroll
        for (int kk = 0; kk < 32; kk++) {
            float4 a  = *(float4*)&sh_in[kk][tn];
            float4 wv = *(float4*)&sh_w[kk][to];
            float av[4] = {a.x, a.y, a.z, a.w};
            float wr[4] = {wv.x, wv.y, wv.z, wv.w};
            #pragma unroll
            for (int i = 0; i < 4; i++)
                #pragma unroll
                for (int j = 0; j < 4; j++)
                    acc[i][j] += wr[i] * av[j];
        }
        __syncthreads();
    }
    #pragma unroll
    for (int i = 0; i < 4; i++) {
        int o = o0 + to + i;
        float bv = bias ? bias[o] : 0.f;
        float v[4];
        #pragma unroll
        for (int j = 0; j < 4; j++) v[j] = acc[i][j] + bv;
        if (act == 1) {
            #pragma unroll
            for (int j = 0; j < 4; j++) v[j] = gelu_f(v[j]);
        }
        size_t base = ((size_t)b*O + o) * NPIX + n0 + tn;
        if (res) {
            float4 r = *(const float4*)(res + base);
            v[0] += r.x; v[1] += r.y; v[2] += r.z; v[3] += r.w;
        }
        float4 ov = {v[0], v[1], v[2], v[3]};
        *(float4*)(out + base) = ov;
    }
}

// ---------------- tensor-core attention: N=4096, c=32, tf32 MMA ----------------
__global__ void __launch_bounds__(128) k_attn_tc(const float* __restrict__ qkv,
                                                 float* __restrict__ av)
{
    __shared__ float sQh[64][36];
    __shared__ float sQl[64][36];
    __shared__ float sKh[32][36];
    __shared__ float sKl[32][36];
    __shared__ float sV [32][36];
    __shared__ float sP [64][36];

    int b    = blockIdx.y;
    int n0   = blockIdx.x * 64;
    int t    = threadIdx.x;
    int warp = t >> 5, lane = t & 31;
    int gr   = lane >> 2;
    int tig  = lane & 3;
    int wrow = warp * 16;

    const float* qb = qkv + (size_t)b * 96 * NPIX;
    const float* kb = qb + 32 * NPIX;
    const float* vb = qb + 64 * NPIX;

    #pragma unroll
    for (int i = 0; i < 16; i++) {
        int flat = i * 128 + t;
        int c = flat >> 6, j = flat & 63;
        float v = qb[c*NPIX + n0 + j] * 0.17677669529663687f;
        float hi = tf32f(v);
        sQh[j][c] = hi;
        sQl[j][c] = tf32f(v - hi);
    }

    float o[4][4] = {};
    float l0 = 0.f, l1 = 0.f;

    for (int t0 = 0; t0 < NPIX; t0 += 32) {
        __syncthreads();
        #pragma unroll
        for (int i = 0; i < 8; i++) {
            int c = i * 4 + warp;
            float kv = kb[c*NPIX + t0 + lane];
            float hi = tf32f(kv);
            sKh[lane][c] = hi;
            sKl[lane][c] = tf32f(kv - hi);
            sV[c][lane]  = tf32f(vb[c*NPIX + t0 + lane]);
        }
        __syncthreads();

        float s[4][4] = {};
        #pragma unroll
        for (int k0 = 0; k0 < 32; k0 += 8) {
            float ah[4], al[4];
            ah[0] = sQh[wrow+gr  ][k0+tig];   ah[1] = sQh[wrow+gr+8][k0+tig];
            ah[2] = sQh[wrow+gr  ][k0+tig+4]; ah[3] = sQh[wrow+gr+8][k0+tig+4];
            al[0] = sQl[wrow+gr  ][k0+tig];   al[1] = sQl[wrow+gr+8][k0+tig];
            al[2] = sQl[wrow+gr  ][k0+tig+4]; al[3] = sQl[wrow+gr+8][k0+tig+4];
            #pragma unroll
            for (int nt = 0; nt < 4; nt++) {
                float bh0 = sKh[nt*8+gr][k0+tig], bh1 = sKh[nt*8+gr][k0+tig+4];
                float bl0 = sKl[nt*8+gr][k0+tig], bl1 = sKl[nt*8+gr][k0+tig+4];
                mma_tf32(s[nt], ah, bh0, bh1);
                mma_tf32(s[nt], ah, bl0, bl1);
                mma_tf32(s[nt], al, bh0, bh1);
            }
        }

        #pragma unroll
        for (int nt = 0; nt < 4; nt++) {
            float p0 = __expf(s[nt][0]);
            float p1 = __expf(s[nt][1]);
            float p2 = __expf(s[nt][2]);
            float p3 = __expf(s[nt][3]);
            l0 += p0 + p1;
            l1 += p2 + p3;
            sP[wrow+gr  ][nt*8 + 2*tig    ] = tf32f(p0);
            sP[wrow+gr  ][nt*8 + 2*tig + 1] = tf32f(p1);
            sP[wrow+gr+8][nt*8 + 2*tig    ] = tf32f(p2);
            sP[wrow+gr+8][nt*8 + 2*tig + 1] = tf32f(p3);
        }
        __syncwarp();

        #pragma unroll
        for (int k0 = 0; k0 < 32; k0 += 8) {
            float a[4];
            a[0] = sP[wrow+gr  ][k0+tig];   a[1] = sP[wrow+gr+8][k0+tig];
            a[2] = sP[wrow+gr  ][k0+tig+4]; a[3] = sP[wrow+gr+8][k0+tig+4];
            #pragma unroll
            for (int ct = 0; ct < 4; ct++) {
                float b0 = sV[ct*8+gr][k0+tig];
                float b1 = sV[ct*8+gr][k0+tig+4];
                mma_tf32(o[ct], a, b0, b1);
            }
        }
    }

    l0 += __shfl_xor_sync(0xffffffffu, l0, 1);
    l0 += __shfl_xor_sync(0xffffffffu, l0, 2);
    l1 += __shfl_xor_sync(0xffffffffu, l1, 1);
    l1 += __shfl_xor_sync(0xffffffffu, l1, 2);
    float inv0 = 1.f / l0, inv1 = 1.f / l1;

    __syncthreads();
    #pragma unroll
    for (int ct = 0; ct < 4; ct++) {
        sP[wrow+gr  ][ct*8 + 2*tig    ] = o[ct][0] * inv0;
        sP[wrow+gr  ][ct*8 + 2*tig + 1] = o[ct][1] * inv0;
        sP[wrow+gr+8][ct*8 + 2*tig    ] = o[ct][2] * inv1;
        sP[wrow+gr+8][ct*8 + 2*tig + 1] = o[ct][3] * inv1;
    }
    __syncthreads();

    #pragma unroll
    for (int i = 0; i < 16; i++) {
        int flat = i * 128 + t;
        int c = flat >> 6, j = flat & 63;
        av[((size_t)b*32 + c)*NPIX + n0 + j] = sP[j][c];
    }
}

// ---------------- LayerNorm v2: 64x64 tile per block, smem-staged ----------------
__global__ void __launch_bounds__(256) k_ln(
    const float* __restrict__ e, const float* __restrict__ g,
    const float* __restrict__ bta, float* __restrict__ outp)
{
    __shared__ float tile[64][65];
    __shared__ float rs[4][64], rs2[4][64];
    __shared__ float smu[64], srstd[64];
    int t  = threadIdx.x;
    int b  = blockIdx.x >> 6;
    int p0 = (blockIdx.x & 63) * 64;
    int pl = t & 63;
    int q  = t >> 6;
    float s = 0.f, s2 = 0.f;
    #pragma unroll 4
    for (int i = 0; i < 16; i++) {
        int c = q*16 + i;
        float v = e[(((size_t)b*64 + c) << 12) + p0 + pl];
        tile[c][pl] = v;
        s += v; s2 += v*v;
    }
    rs[q][pl] = s; rs2[q][pl] = s2;
    __syncthreads();
    if (t < 64) {
        float ss = rs[0][t] + rs[1][t] + rs[2][t] + rs[3][t];
        float qq = rs2[0][t] + rs2[1][t] + rs2[2][t] + rs2[3][t];
        float mu = ss * (1.f/64.f);
        float var = qq * (1.f/64.f) - mu*mu;
        smu[t] = mu;
        srstd[t] = rsqrtf(var + 1e-5f);
    }
    __syncthreads();
    float mu = smu[pl], rstd = srstd[pl];
    #pragma unroll 4
    for (int i = 0; i < 16; i++) {
        int c = q*16 + i;
        outp[(((size_t)b*64 + c) << 12) + p0 + pl] = (tile[c][pl] - mu)*rstd*g[c] + bta[c];
    }
}

// ---------------- depthwise 3x3 + gelu ----------------
__global__ void k_dw(const float* __restrict__ h1, const float* __restrict__ w,
                     const float* __restrict__ bias, float* __restrict__ h2)
{
    int idx = blockIdx.x * blockDim.x + threadIdx.x;
    if (idx >= BATCH * 256 * NPIX) return;
    int p = idx & 4095, c = (idx >> 12) & 255;
    int y = p >> 6, x = p & 63;
    const float* src = h1 + ((size_t)idx - p);
    const float* wc = w + c * 9;
    float acc = bias[c];
    #pragma unroll
    for (int dy = -1; dy <= 1; dy++)
        #pragma unroll
        for (int dx = -1; dx <= 1; dx++) {
            int yy = y + dy, xx = x + dx;
            if ((unsigned)yy < 64u && (unsigned)xx < 64u)
                acc += src[yy*64 + xx] * wc[(dy+1)*3 + (dx+1)];
        }
    h2[idx] = gelu_f(acc);
}

// ---------------- host ----------------
extern "C" void kernel_launch(void* const* d_in, const int* in_sizes, int n_in,
                              void* d_out, int out_size)
{
    const float* x        = (const float*)d_in[0];
    const float* skip     = (const float*)d_in[1];
    const float* qkv_w    = (const float*)d_in[2];
    const float* qkv_b    = (const float*)d_in[3];
    const float* proj_w   = (const float*)d_in[4];
    const float* proj_b   = (const float*)d_in[5];
    const float* edge_w   = (const float*)d_in[6];
    const float* thick_w  = (const float*)d_in[7];
    const float* thick_b  = (const float*)d_in[8];
    const float* off_w    = (const float*)d_in[9];
    const float* off_b    = (const float*)d_in[10];
    const float* deform_w = (const float*)d_in[11];
    const float* deform_b = (const float*)d_in[12];
    const float* ln_g     = (const float*)d_in[13];
    const float* ln_b     = (const float*)d_in[14];
    const float* mlp1_w   = (const float*)d_in[15];
    const float* mlp1_b   = (const float*)d_in[16];
    const float* dw_w     = (const float*)d_in[17];
    const float* dw_b     = (const float*)d_in[18];
    const float* mlp2_w   = (const float*)d_in[19];
    const float* mlp2_b   = (const float*)d_in[20];
    const float* down_w   = (const float*)d_in[21];
    const float* down_b   = (const float*)d_in[22];
    const float* up_w     = (const float*)d_in[23];
    const float* up_b     = (const float*)d_in[24];
    float* out = (float*)d_out;

    float *skipu, *meanv, *thick, *qkv, *avb, *x2, *edge, *col, *off, *offw, *offb;
    float *dd, *e, *ln, *h1, *h2, *tt;
    cudaGetSymbolAddress((void**)&skipu, g_skipu);
    cudaGetSymbolAddress((void**)&meanv, g_mean);
    cudaGetSymbolAddress((void**)&thick, g_thick);
    cudaGetSymbolAddress((void**)&qkv,   g_qkv);
    cudaGetSymbolAddress((void**)&avb,   g_av);
    cudaGetSymbolAddress((void**)&x2,    g_x2);
    cudaGetSymbolAddress((void**)&edge,  g_edge);
    cudaGetSymbolAddress((void**)&col,   g_col);
    cudaGetSymbolAddress((void**)&off,   g_off);
    cudaGetSymbolAddress((void**)&offw,  g_offw);
    cudaGetSymbolAddress((void**)&offb,  g_offb);
    cudaGetSymbolAddress((void**)&dd,    g_d);
    cudaGetSymbolAddress((void**)&e,     g_e);
    cudaGetSymbolAddress((void**)&ln,    g_ln);
    cudaGetSymbolAddress((void**)&h1,    g_h1);
    cudaGetSymbolAddress((void**)&h2,    g_h2);
    cudaGetSymbolAddress((void**)&tt,    g_t);

    // attention branch
    k_gemm<<<dim3(32, 3, 4), 256>>>(x, nullptr, 256, 256, qkv_w, qkv_b, nullptr, 0, qkv, 96);
    k_attn_tc<<<dim3(64, 4), 128>>>(qkv, avb);
    k_gemm<<<dim3(32, 8, 4), 256>>>(avb, nullptr, 32, 32, proj_w, proj_b, x, 0, x2, 256);

    // skip branch
    k_upsample<<<256, 256>>>(skip, thick_w, thick_b, skipu, meanv, thick);
    k_edge<<<(BATCH*SKIPCH*NPIX + 255)/256, 256>>>(meanv, edge_w, edge);
    k_im2col<<<(BATCH*576*NPIX + 255)/256, 256>>>(edge, col);
    k_prep_offw<<<(32*576 + 255)/256, 256>>>(off_w, off_b, offw, offb);
    k_gemm<<<dim3(32, 1, 4), 256>>>(col, nullptr, 576, 576, offw, offb, nullptr, 0, off, 32);
    k_sample<<<(BATCH*9*8*NPIX + 255)/256, 256>>>(off, thick, skipu, col);
    k_gemm<<<dim3(32, 2, 4), 256>>>(col, nullptr, 576, 576, deform_w, deform_b, edge, 0, dd, 64);

    // merge + token mixer
    k_gemm<<<dim3(32, 2, 4), 256>>>(x2, dd, 320, 256, down_w, down_b, nullptr, 0, e, 64);
    k_ln<<<256, 256>>>(e, ln_g, ln_b, ln);
    k_gemm<<<dim3(32, 8, 4), 256>>>(ln, nullptr, 64, 64, mlp1_w, mlp1_b, nullptr, 1, h1, 256);
    k_dw<<<(BATCH*256*NPIX + 255)/256, 256>>>(h1, dw_w, dw_b, h2);
    k_gemm<<<dim3(32, 2, 4), 256>>>(h2, nullptr, 256, 256, mlp2_w, mlp2_b, e, 0, tt, 64);
    k_gemm<<<dim3(32, 8, 4), 256>>>(tt, nullptr, 64, 64, up_w, up_b, nullptr, 0, out, 256);
}

// round 13
// speedup vs baseline: 1.3377x; 1.0272x over previous
#include <cuda_runtime.h>
#include <math.h>

#define BATCH 4
#define INCH 256
#define SKIPCH 64
#define EMBEDC 64
#define NPIX 4096   // 64*64

// ---------------- scratch (static device globals; no allocation) ----------------
__device__ float g_skipu[BATCH*SKIPCH*NPIX];
__device__ float g_mean [BATCH*NPIX];
__device__ float g_thick[BATCH*NPIX];
__device__ float g_qkv  [BATCH*96*NPIX];
__device__ float g_av   [BATCH*32*NPIX];
__device__ float g_x2   [BATCH*INCH*NPIX];
__device__ float g_edge [BATCH*SKIPCH*NPIX];
__device__ float g_col  [BATCH*576*NPIX];
__device__ float g_off  [BATCH*32*NPIX];
__device__ float g_offw [32*576];
__device__ float g_offb [32];
__device__ float g_d    [BATCH*SKIPCH*NPIX];
__device__ float g_e    [BATCH*EMBEDC*NPIX];
__device__ float g_ln   [BATCH*EMBEDC*NPIX];
__device__ float g_h1   [BATCH*256*NPIX];
__device__ float g_h2   [BATCH*256*NPIX];
__device__ float g_t    [BATCH*EMBEDC*NPIX];

__device__ __forceinline__ float gelu_f(float v) {
    return 0.5f * v * (1.0f + erff(v * 0.70710678118654752f));
}

__device__ __forceinline__ float tf32f(float x) {
    unsigned u;
    asm("cvt.rna.tf32.f32 %0, %1;" : "=r"(u) : "f"(x));
    return __uint_as_float(u);
}

__device__ __forceinline__ void mma_tf32(float* d, const float* a, float b0, float b1) {
    asm volatile("mma.sync.aligned.m16n8k8.row.col.f32.tf32.tf32.f32 "
        "{%0,%1,%2,%3}, {%4,%5,%6,%7}, {%8,%9}, {%0,%1,%2,%3};"
        : "+f"(d[0]), "+f"(d[1]), "+f"(d[2]), "+f"(d[3])
        : "r"(__float_as_uint(a[0])), "r"(__float_as_uint(a[1])),
          "r"(__float_as_uint(a[2])), "r"(__float_as_uint(a[3])),
          "r"(__float_as_uint(b0)), "r"(__float_as_uint(b1)));
}

// ---------------- upsample v2: 64 pixels x 4 channel-groups per block ----------------
__global__ void __launch_bounds__(256) k_upsample(
    const float* __restrict__ skip, const float* __restrict__ thick_w,
    const float* __restrict__ thick_b,
    float* __restrict__ skipu, float* __restrict__ meanv, float* __restrict__ thick)
{
    __shared__ float red_s[4][64];
    __shared__ float red_t[4][64];
    int t  = threadIdx.x;
    int b  = blockIdx.x >> 6;
    int p0 = (blockIdx.x & 63) * 64;
    int pl = t & 63;
    int q  = t >> 6;
    int p  = p0 + pl;
    int oy = p >> 6, ox = p & 63;
    float sy = oy * 0.5f - 0.25f, sx = ox * 0.5f - 0.25f;
    float y0f = floorf(sy), x0f = floorf(sx);
    float wy = sy - y0f, wx = sx - x0f;
    int y0 = (int)y0f, x0 = (int)x0f;
    int y0c = min(max(y0, 0), 31), y1c = min(max(y0 + 1, 0), 31);
    int x0c = min(max(x0, 0), 31), x1c = min(max(x0 + 1, 0), 31);
    float w00 = (1.f - wy) * (1.f - wx), w01 = (1.f - wy) * wx;
    float w10 = wy * (1.f - wx), w11 = wy * wx;
    int i00 = y0c*32 + x0c, i01 = y0c*32 + x1c;
    int i10 = y1c*32 + x0c, i11 = y1c*32 + x1c;
    const float* sb = skip + (size_t)b * SKIPCH * 1024;
    float s = 0.f, ta = 0.f;
    #pragma unroll 4
    for (int i = 0; i < 16; i++) {
        int c = q*16 + i;
        const float* pc = sb + c * 1024;
        float v = w00*pc[i00] + w01*pc[i01] + w10*pc[i10] + w11*pc[i11];
        skipu[((size_t)(b*SKIPCH + c)) * NPIX + p] = v;
        s += v;
        ta += v * thick_w[c];
    }
    red_s[q][pl] = s; red_t[q][pl] = ta;
    __syncthreads();
    if (t < 64) {
        float ss = red_s[0][t] + red_s[1][t] + red_s[2][t] + red_s[3][t];
        float tt = red_t[0][t] + red_t[1][t] + red_t[2][t] + red_t[3][t];
        meanv[b*NPIX + p0 + t] = ss * (1.0f / 64.0f);
        thick[b*NPIX + p0 + t] = 1.0f / (1.0f + __expf(-(tt + thick_b[0])));
    }
}

// ---------------- edge conv: 3x3, 1->64 ch, no bias, zero pad ----------------
__global__ void k_edge(const float* __restrict__ meanv, const float* __restrict__ edge_w,
                       float* __restrict__ edge)
{
    int idx = blockIdx.x * blockDim.x + threadIdx.x;
    if (idx >= BATCH * SKIPCH * NPIX) return;
    int p = idx & 4095, oc = (idx >> 12) & 63, b = idx >> 18;
    int y = p >> 6, x = p & 63;
    const float* mb = meanv + b * NPIX;
    const float* w = edge_w + oc * 9;
    float acc = 0.f;
    #pragma unroll
    for (int dy = -1; dy <= 1; dy++)
        #pragma unroll
        for (int dx = -1; dx <= 1; dx++) {
            int yy = y + dy, xx = x + dx;
            if ((unsigned)yy < 64u && (unsigned)xx < 64u)
                acc += mb[yy*64 + xx] * w[(dy+1)*3 + (dx+1)];
        }
    edge[idx] = acc;
}

// ---------------- im2col of edge ----------------
__global__ void k_im2col(const float* __restrict__ edge, float* __restrict__ col)
{
    int idx = blockIdx.x * blockDim.x + threadIdx.x;
    if (idx >= BATCH * 576 * NPIX) return;
    int p = idx & 4095;
    int r = (idx >> 12) % 576;
    int b = idx / (576 * NPIX);
    int ic = r / 9, tap = r % 9;
    int y = (p >> 6) + tap/3 - 1, x = (p & 63) + tap%3 - 1;
    float v = 0.f;
    if ((unsigned)y < 64u && (unsigned)x < 64u)
        v = edge[(((size_t)b*64 + ic) << 12) + y*64 + x];
    col[idx] = v;
}

// ---------------- pad off weights 18 -> 32 rows ----------------
__global__ void k_prep_offw(const float* __restrict__ off_w, const float* __restrict__ off_b,
                            float* __restrict__ wpad, float* __restrict__ bpad)
{
    int idx = blockIdx.x * blockDim.x + threadIdx.x;
    if (idx < 32 * 576) {
        int o = idx / 576, k = idx % 576;
        wpad[idx] = (o < 18) ? off_w[o*576 + k] : 0.f;
    }
    if (idx < 32) bpad[idx] = (idx < 18) ? off_b[idx] : 0.f;
}

// ---------------- sample v2: guide fused, 8-channel groups ----------------
__global__ void __launch_bounds__(256) k_sample(
    const float* __restrict__ off, const float* __restrict__ thick,
    const float* __restrict__ skipu, float* __restrict__ col)
{
    int idx = blockIdx.x * blockDim.x + threadIdx.x;
    if (idx >= BATCH * 9 * 8 * NPIX) return;
    int p    = idx & 4095;
    int rest = idx >> 12;
    int g8   = rest & 7;  rest >>= 3;
    int k    = rest % 9;
    int b    = rest / 9;
    float guide = 1.f + 16.f * thick[b*NPIX + p];
    float dy = off[(((size_t)b*32 + 2*k    ) << 12) + p] * guide;
    float dx = off[(((size_t)b*32 + 2*k + 1) << 12) + p] * guide;
    float py = (float)(p >> 6) + (float)(k/3 - 1) + dy;
    float px = (float)(p & 63) + (float)(k%3 - 1) + dx;
    float y0f = floorf(py), x0f = floorf(px);
    float wy = py - y0f, wx = px - x0f;
    int y0 = (int)y0f, x0 = (int)x0f;
    int y1 = y0 + 1, x1 = x0 + 1;
    float vy0 = (y0 >= 0 && y0 < 64) ? 1.f : 0.f;
    float vy1 = (y1 >= 0 && y1 < 64) ? 1.f : 0.f;
    float vx0 = (x0 >= 0 && x0 < 64) ? 1.f : 0.f;
    float vx1 = (x1 >= 0 && x1 < 64) ? 1.f : 0.f;
    int y0c = min(max(y0,0),63), y1c = min(max(y1,0),63);
    int x0c = min(max(x0,0),63), x1c = min(max(x1,0),63);
    float w00 = (1.f-wy)*(1.f-wx)*vy0*vx0;
    float w01 = (1.f-wy)*wx      *vy0*vx1;
    float w10 = wy*(1.f-wx)      *vy1*vx0;
    float w11 = wy*wx            *vy1*vx1;
    int i00 = y0c*64+x0c, i01 = y0c*64+x1c, i10 = y1c*64+x0c, i11 = y1c*64+x1c;
    const float* sb = skipu + (size_t)b * SKIPCH * NPIX;
    #pragma unroll
    for (int i = 0; i < 8; i++) {
        int ic = g8*8 + i;
        const float* pc = sb + ic * NPIX;
        float v = w00*pc[i00] + w01*pc[i01] + w10*pc[i10] + w11*pc[i11];
        col[(((size_t)(b*64 + ic))*9 + k) * NPIX + p] = v;
    }
}

// ---------------- 1x1-conv GEMM v3: FFMA + register-prefetch double buffer ----------------
// TM outputs x 128 pixels per block, 256 threads. TM in {32, 64}.
// Same k-ascending accumulation order as v2 -> identical numerics.
template<int TM>
__global__ void __launch_bounds__(256) k_gemm(
    const float* __restrict__ inA, const float* __restrict__ inB, int K, int K1,
    const float* __restrict__ w, const float* __restrict__ bias,
    const float* __restrict__ res, int act,
    float* __restrict__ out, int O)
{
    constexpr int OPT = TM / 8;   // outputs per thread (4 or 8)
    __shared__ __align__(16) float sh_in[32][128];
    __shared__ __align__(16) float sh_w[32][TM + 4];

    int b  = blockIdx.z;
    int o0 = blockIdx.y * TM;
    int n0 = blockIdx.x * 128;
    int t  = threadIdx.x;
    int tn = (t & 31) * 4;
    int to = (t >> 5) * OPT;
    int kr = t >> 5;      // 0..7
    int kc = t & 31;      // 0..31
    int KB = K - K1;

    float acc[OPT][4] = {};
    float4 rin[4];
    float  rw[OPT];

    // prefetch tile 0
    {
        #pragma unroll
        for (int i = 0; i < 4; i++) {
            int k = kr + i*8;
            const float* src = (k < K1)
                ? (inA + ((size_t)b*K1 + k) * NPIX)
                : (inB + ((size_t)b*KB + (k - K1)) * NPIX);
            rin[i] = *(const float4*)(src + n0 + tn);
        }
        #pragma unroll
        for (int i = 0; i < OPT; i++)
            rw[i] = w[(size_t)(o0 + kr + i*8) * K + kc];
    }

    for (int k0 = 0; k0 < K; k0 += 32) {
        // commit prefetched tile to smem
        #pragma unroll
        for (int i = 0; i < 4; i++)
            *(float4*)&sh_in[kr + i*8][tn] = rin[i];
        #pragma unroll
        for (int i = 0; i < OPT; i++)
            sh_w[kc][kr + i*8] = rw[i];
        __syncthreads();

        // prefetch next tile (overlaps with compute below)
        int kn = k0 + 32;
        if (kn < K) {
            #pragma unroll
            for (int i = 0; i < 4; i++) {
                int k = kn + kr + i*8;
                const float* src = (k < K1)
                    ? (inA + ((size_t)b*K1 + k) * NPIX)
                    : (inB + ((size_t)b*KB + (k - K1)) * NPIX);
                rin[i] = *(const float4*)(src + n0 + tn);
            }
            #pragma unroll
            for (int i = 0; i < OPT; i++)
                rw[i] = w[(size_t)(o0 + kr + i*8) * K + kn + kc];
        }

        // compute on staged tile
        #pragma unroll
        for (int kk = 0; kk < 32; kk++) {
            float4 a = *(float4*)&sh_in[kk][tn];
            float av[4] = {a.x, a.y, a.z, a.w};
            float wr[OPT];
            #pragma unroll
            for (int i = 0; i < OPT; i += 4) {
                float4 wv = *(float4*)&sh_w[kk][to + i];
                wr[i] = wv.x; wr[i+1] = wv.y; wr[i+2] = wv.z; wr[i+3] = wv.w;
            }
            #pragma unroll
            for (int i = 0; i < OPT; i++)
                #pragma unroll
                for (int j = 0; j < 4; j++)
                    acc[i][j] += wr[i] * av[j];
        }
        __syncthreads();
    }

    #pragma unroll
    for (int i = 0; i < OPT; i++) {
        int o = o0 + to + i;
        float bv = bias ? bias[o] : 0.f;
        float v[4];
        #pragma unroll
        for (int j = 0; j < 4; j++) v[j] = acc[i][j] + bv;
        if (act == 1) {
            #pragma unroll
            for (int j = 0; j < 4; j++) v[j] = gelu_f(v[j]);
        }
        size_t base = ((size_t)b*O + o) * NPIX + n0 + tn;
        if (res) {
            float4 r = *(const float4*)(res + base);
            v[0] += r.x; v[1] += r.y; v[2] += r.z; v[3] += r.w;
        }
        float4 ov = {v[0], v[1], v[2], v[3]};
        *(float4*)(out + base) = ov;
    }
}

// ---------------- tensor-core attention: N=4096, c=32, tf32 MMA ----------------
__global__ void __launch_bounds__(128) k_attn_tc(const float* __restrict__ qkv,
                                                 float* __restrict__ av)
{
    __shared__ float sQh[64][36];
    __shared__ float sQl[64][36];
    __shared__ float sKh[32][36];
    __shared__ float sKl[32][36];
    __shared__ float sV [32][36];
    __shared__ float sP [64][36];

    int b    = blockIdx.y;
    int n0   = blockIdx.x * 64;
    int t    = threadIdx.x;
    int warp = t >> 5, lane = t & 31;
    int gr   = lane >> 2;
    int tig  = lane & 3;
    int wrow = warp * 16;

    const float* qb = qkv + (size_t)b * 96 * NPIX;
    const float* kb = qb + 32 * NPIX;
    const float* vb = qb + 64 * NPIX;

    #pragma unroll
    for (int i = 0; i < 16; i++) {
        int flat = i * 128 + t;
        int c = flat >> 6, j = flat & 63;
        float v = qb[c*NPIX + n0 + j] * 0.17677669529663687f;
        float hi = tf32f(v);
        sQh[j][c] = hi;
        sQl[j][c] = tf32f(v - hi);
    }

    float o[4][4] = {};
    float l0 = 0.f, l1 = 0.f;

    for (int t0 = 0; t0 < NPIX; t0 += 32) {
        __syncthreads();
        #pragma unroll
        for (int i = 0; i < 8; i++) {
            int c = i * 4 + warp;
            float kv = kb[c*NPIX + t0 + lane];
            float hi = tf32f(kv);
            sKh[lane][c] = hi;
            sKl[lane][c] = tf32f(kv - hi);
            sV[c][lane]  = tf32f(vb[c*NPIX + t0 + lane]);
        }
        __syncthreads();

        float s[4][4] = {};
        #pragma unroll
        for (int k0 = 0; k0 < 32; k0 += 8) {
            float ah[4], al[4];
            ah[0] = sQh[wrow+gr  ][k0+tig];   ah[1] = sQh[wrow+gr+8][k0+tig];
            ah[2] = sQh[wrow+gr  ][k0+tig+4]; ah[3] = sQh[wrow+gr+8][k0+tig+4];
            al[0] = sQl[wrow+gr  ][k0+tig];   al[1] = sQl[wrow+gr+8][k0+tig];
            al[2] = sQl[wrow+gr  ][k0+tig+4]; al[3] = sQl[wrow+gr+8][k0+tig+4];
            #pragma unroll
            for (int nt = 0; nt < 4; nt++) {
                float bh0 = sKh[nt*8+gr][k0+tig], bh1 = sKh[nt*8+gr][k0+tig+4];
                float bl0 = sKl[nt*8+gr][k0+tig], bl1 = sKl[nt*8+gr][k0+tig+4];
                mma_tf32(s[nt], ah, bh0, bh1);
                mma_tf32(s[nt], ah, bl0, bl1);
                mma_tf32(s[nt], al, bh0, bh1);
            }
        }

        #pragma unroll
        for (int nt = 0; nt < 4; nt++) {
            float p0 = __expf(s[nt][0]);
            float p1 = __expf(s[nt][1]);
            float p2 = __expf(s[nt][2]);
            float p3 = __expf(s[nt][3]);
            l0 += p0 + p1;
            l1 += p2 + p3;
            sP[wrow+gr  ][nt*8 + 2*tig    ] = tf32f(p0);
            sP[wrow+gr  ][nt*8 + 2*tig + 1] = tf32f(p1);
            sP[wrow+gr+8][nt*8 + 2*tig    ] = tf32f(p2);
            sP[wrow+gr+8][nt*8 + 2*tig + 1] = tf32f(p3);
        }
        __syncwarp();

        #pragma unroll
        for (int k0 = 0; k0 < 32; k0 += 8) {
            float a[4];
            a[0] = sP[wrow+gr  ][k0+tig];   a[1] = sP[wrow+gr+8][k0+tig];
            a[2] = sP[wrow+gr  ][k0+tig+4]; a[3] = sP[wrow+gr+8][k0+tig+4];
            #pragma unroll
            for (int ct = 0; ct < 4; ct++) {
                float b0 = sV[ct*8+gr][k0+tig];
                float b1 = sV[ct*8+gr][k0+tig+4];
                mma_tf32(o[ct], a, b0, b1);
            }
        }
    }

    l0 += __shfl_xor_sync(0xffffffffu, l0, 1);
    l0 += __shfl_xor_sync(0xffffffffu, l0, 2);
    l1 += __shfl_xor_sync(0xffffffffu, l1, 1);
    l1 += __shfl_xor_sync(0xffffffffu, l1, 2);
    float inv0 = 1.f / l0, inv1 = 1.f / l1;

    __syncthreads();
    #pragma unroll
    for (int ct = 0; ct < 4; ct++) {
        sP[wrow+gr  ][ct*8 + 2*tig    ] = o[ct][0] * inv0;
        sP[wrow+gr  ][ct*8 + 2*tig + 1] = o[ct][1] * inv0;
        sP[wrow+gr+8][ct*8 + 2*tig    ] = o[ct][2] * inv1;
        sP[wrow+gr+8][ct*8 + 2*tig + 1] = o[ct][3] * inv1;
    }
    __syncthreads();

    #pragma unroll
    for (int i = 0; i < 16; i++) {
        int flat = i * 128 + t;
        int c = flat >> 6, j = flat & 63;
        av[((size_t)b*32 + c)*NPIX + n0 + j] = sP[j][c];
    }
}

// ---------------- LayerNorm v2: 64x64 tile per block, smem-staged ----------------
__global__ void __launch_bounds__(256) k_ln(
    const float* __restrict__ e, const float* __restrict__ g,
    const float* __restrict__ bta, float* __restrict__ outp)
{
    __shared__ float tile[64][65];
    __shared__ float rs[4][64], rs2[4][64];
    __shared__ float smu[64], srstd[64];
    int t  = threadIdx.x;
    int b  = blockIdx.x >> 6;
    int p0 = (blockIdx.x & 63) * 64;
    int pl = t & 63;
    int q  = t >> 6;
    float s = 0.f, s2 = 0.f;
    #pragma unroll 4
    for (int i = 0; i < 16; i++) {
        int c = q*16 + i;
        float v = e[(((size_t)b*64 + c) << 12) + p0 + pl];
        tile[c][pl] = v;
        s += v; s2 += v*v;
    }
    rs[q][pl] = s; rs2[q][pl] = s2;
    __syncthreads();
    if (t < 64) {
        float ss = rs[0][t] + rs[1][t] + rs[2][t] + rs[3][t];
        float qq = rs2[0][t] + rs2[1][t] + rs2[2][t] + rs2[3][t];
        float mu = ss * (1.f/64.f);
        float var = qq * (1.f/64.f) - mu*mu;
        smu[t] = mu;
        srstd[t] = rsqrtf(var + 1e-5f);
    }
    __syncthreads();
    float mu = smu[pl], rstd = srstd[pl];
    #pragma unroll 4
    for (int i = 0; i < 16; i++) {
        int c = q*16 + i;
        outp[(((size_t)b*64 + c) << 12) + p0 + pl] = (tile[c][pl] - mu)*rstd*g[c] + bta[c];
    }
}

// ---------------- depthwise 3x3 + gelu ----------------
__global__ void k_dw(const float* __restrict__ h1, const float* __restrict__ w,
                     const float* __restrict__ bias, float* __restrict__ h2)
{
    int idx = blockIdx.x * blockDim.x + threadIdx.x;
    if (idx >= BATCH * 256 * NPIX) return;
    int p = idx & 4095, c = (idx >> 12) & 255;
    int y = p >> 6, x = p & 63;
    const float* src = h1 + ((size_t)idx - p);
    const float* wc = w + c * 9;
    float acc = bias[c];
    #pragma unroll
    for (int dy = -1; dy <= 1; dy++)
        #pragma unroll
        for (int dx = -1; dx <= 1; dx++) {
            int yy = y + dy, xx = x + dx;
            if ((unsigned)yy < 64u && (unsigned)xx < 64u)
                acc += src[yy*64 + xx] * wc[(dy+1)*3 + (dx+1)];
        }
    h2[idx] = gelu_f(acc);
}

// ---------------- host ----------------
extern "C" void kernel_launch(void* const* d_in, const int* in_sizes, int n_in,
                              void* d_out, int out_size)
{
    const float* x        = (const float*)d_in[0];
    const float* skip     = (const float*)d_in[1];
    const float* qkv_w    = (const float*)d_in[2];
    const float* qkv_b    = (const float*)d_in[3];
    const float* proj_w   = (const float*)d_in[4];
    const float* proj_b   = (const float*)d_in[5];
    const float* edge_w   = (const float*)d_in[6];
    const float* thick_w  = (const float*)d_in[7];
    const float* thick_b  = (const float*)d_in[8];
    const float* off_w    = (const float*)d_in[9];
    const float* off_b    = (const float*)d_in[10];
    const float* deform_w = (const float*)d_in[11];
    const float* deform_b = (const float*)d_in[12];
    const float* ln_g     = (const float*)d_in[13];
    const float* ln_b     = (const float*)d_in[14];
    const float* mlp1_w   = (const float*)d_in[15];
    const float* mlp1_b   = (const float*)d_in[16];
    const float* dw_w     = (const float*)d_in[17];
    const float* dw_b     = (const float*)d_in[18];
    const float* mlp2_w   = (const float*)d_in[19];
    const float* mlp2_b   = (const float*)d_in[20];
    const float* down_w   = (const float*)d_in[21];
    const float* down_b   = (const float*)d_in[22];
    const float* up_w     = (const float*)d_in[23];
    const float* up_b     = (const float*)d_in[24];
    float* out = (float*)d_out;

    float *skipu, *meanv, *thick, *qkv, *avb, *x2, *edge, *col, *off, *offw, *offb;
    float *dd, *e, *ln, *h1, *h2, *tt;
    cudaGetSymbolAddress((void**)&skipu, g_skipu);
    cudaGetSymbolAddress((void**)&meanv, g_mean);
    cudaGetSymbolAddress((void**)&thick, g_thick);
    cudaGetSymbolAddress((void**)&qkv,   g_qkv);
    cudaGetSymbolAddress((void**)&avb,   g_av);
    cudaGetSymbolAddress((void**)&x2,    g_x2);
    cudaGetSymbolAddress((void**)&edge,  g_edge);
    cudaGetSymbolAddress((void**)&col,   g_col);
    cudaGetSymbolAddress((void**)&off,   g_off);
    cudaGetSymbolAddress((void**)&offw,  g_offw);
    cudaGetSymbolAddress((void**)&offb,  g_offb);
    cudaGetSymbolAddress((void**)&dd,    g_d);
    cudaGetSymbolAddress((void**)&e,     g_e);
    cudaGetSymbolAddress((void**)&ln,    g_ln);
    cudaGetSymbolAddress((void**)&h1,    g_h1);
    cudaGetSymbolAddress((void**)&h2,    g_h2);
    cudaGetSymbolAddress((void**)&tt,    g_t);

    // attention branch
    k_gemm<32><<<dim3(32, 3, 4), 256>>>(x, nullptr, 256, 256, qkv_w, qkv_b, nullptr, 0, qkv, 96);
    k_attn_tc<<<dim3(64, 4), 128>>>(qkv, avb);
    k_gemm<64><<<dim3(32, 4, 4), 256>>>(avb, nullptr, 32, 32, proj_w, proj_b, x, 0, x2, 256);

    // skip branch
    k_upsample<<<256, 256>>>(skip, thick_w, thick_b, skipu, meanv, thick);
    k_edge<<<(BATCH*SKIPCH*NPIX + 255)/256, 256>>>(meanv, edge_w, edge);
    k_im2col<<<(BATCH*576*NPIX + 255)/256, 256>>>(edge, col);
    k_prep_offw<<<(32*576 + 255)/256, 256>>>(off_w, off_b, offw, offb);
    k_gemm<32><<<dim3(32, 1, 4), 256>>>(col, nullptr, 576, 576, offw, offb, nullptr, 0, off, 32);
    k_sample<<<(BATCH*9*8*NPIX + 255)/256, 256>>>(off, thick, skipu, col);
    k_gemm<64><<<dim3(32, 1, 4), 256>>>(col, nullptr, 576, 576, deform_w, deform_b, edge, 0, dd, 64);

    // merge + token mixer
    k_gemm<64><<<dim3(32, 1, 4), 256>>>(x2, dd, 320, 256, down_w, down_b, nullptr, 0, e, 64);
    k_ln<<<256, 256>>>(e, ln_g, ln_b, ln);
    k_gemm<64><<<dim3(32, 4, 4), 256>>>(ln, nullptr, 64, 64, mlp1_w, mlp1_b, nullptr, 1, h1, 256);
    k_dw<<<(BATCH*256*NPIX + 255)/256, 256>>>(h1, dw_w, dw_b, h2);
    k_gemm<64><<<dim3(32, 1, 4), 256>>>(h2, nullptr, 256, 256, mlp2_w, mlp2_b, e, 0, tt, 64);
    k_gemm<64><<<dim3(32, 4, 4), 256>>>(tt, nullptr, 64, 64, up_w, up_b, nullptr, 0, out, 256);
}

// round 15
// speedup vs baseline: 1.4023x; 1.0483x over previous
#include <cuda_runtime.h>
#include <math.h>

#define BATCH 4
#define INCH 256
#define SKIPCH 64
#define EMBEDC 64
#define NPIX 4096   // 64*64

// ---------------- scratch (static device globals; no allocation) ----------------
__device__ float g_skipu[BATCH*SKIPCH*NPIX];
__device__ float g_mean [BATCH*NPIX];
__device__ float g_thick[BATCH*NPIX];
__device__ float g_qkv  [BATCH*96*NPIX];
__device__ float g_av   [BATCH*32*NPIX];
__device__ float g_x2   [BATCH*INCH*NPIX];
__device__ float g_edge [BATCH*SKIPCH*NPIX];
__device__ float g_col  [BATCH*576*NPIX];
__device__ float g_off  [BATCH*32*NPIX];
__device__ float g_offw [32*576];
__device__ float g_offb [32];
__device__ float g_d    [BATCH*SKIPCH*NPIX];
__device__ float g_e    [BATCH*EMBEDC*NPIX];
__device__ float g_ln   [BATCH*EMBEDC*NPIX];
__device__ float g_h1   [BATCH*256*NPIX];
__device__ float g_h2   [BATCH*256*NPIX];
__device__ float g_t    [BATCH*EMBEDC*NPIX];

__device__ __forceinline__ float gelu_f(float v) {
    return 0.5f * v * (1.0f + erff(v * 0.70710678118654752f));
}

__device__ __forceinline__ float tf32f(float x) {
    unsigned u;
    asm("cvt.rna.tf32.f32 %0, %1;" : "=r"(u) : "f"(x));
    return __uint_as_float(u);
}

__device__ __forceinline__ void mma_tf32(float* d, const float* a, float b0, float b1) {
    asm volatile("mma.sync.aligned.m16n8k8.row.col.f32.tf32.tf32.f32 "
        "{%0,%1,%2,%3}, {%4,%5,%6,%7}, {%8,%9}, {%0,%1,%2,%3};"
        : "+f"(d[0]), "+f"(d[1]), "+f"(d[2]), "+f"(d[3])
        : "r"(__float_as_uint(a[0])), "r"(__float_as_uint(a[1])),
          "r"(__float_as_uint(a[2])), "r"(__float_as_uint(a[3])),
          "r"(__float_as_uint(b0)), "r"(__float_as_uint(b1)));
}

// ---------------- upsample v2: 64 pixels x 4 channel-groups per block ----------------
__global__ void __launch_bounds__(256) k_upsample(
    const float* __restrict__ skip, const float* __restrict__ thick_w,
    const float* __restrict__ thick_b,
    float* __restrict__ skipu, float* __restrict__ meanv, float* __restrict__ thick)
{
    __shared__ float red_s[4][64];
    __shared__ float red_t[4][64];
    int t  = threadIdx.x;
    int b  = blockIdx.x >> 6;
    int p0 = (blockIdx.x & 63) * 64;
    int pl = t & 63;
    int q  = t >> 6;
    int p  = p0 + pl;
    int oy = p >> 6, ox = p & 63;
    float sy = oy * 0.5f - 0.25f, sx = ox * 0.5f - 0.25f;
    float y0f = floorf(sy), x0f = floorf(sx);
    float wy = sy - y0f, wx = sx - x0f;
    int y0 = (int)y0f, x0 = (int)x0f;
    int y0c = min(max(y0, 0), 31), y1c = min(max(y0 + 1, 0), 31);
    int x0c = min(max(x0, 0), 31), x1c = min(max(x0 + 1, 0), 31);
    float w00 = (1.f - wy) * (1.f - wx), w01 = (1.f - wy) * wx;
    float w10 = wy * (1.f - wx), w11 = wy * wx;
    int i00 = y0c*32 + x0c, i01 = y0c*32 + x1c;
    int i10 = y1c*32 + x0c, i11 = y1c*32 + x1c;
    const float* sb = skip + (size_t)b * SKIPCH * 1024;
    float s = 0.f, ta = 0.f;
    #pragma unroll 4
    for (int i = 0; i < 16; i++) {
        int c = q*16 + i;
        const float* pc = sb + c * 1024;
        float v = w00*pc[i00] + w01*pc[i01] + w10*pc[i10] + w11*pc[i11];
        skipu[((size_t)(b*SKIPCH + c)) * NPIX + p] = v;
        s += v;
        ta += v * thick_w[c];
    }
    red_s[q][pl] = s; red_t[q][pl] = ta;
    __syncthreads();
    if (t < 64) {
        float ss = red_s[0][t] + red_s[1][t] + red_s[2][t] + red_s[3][t];
        float tt = red_t[0][t] + red_t[1][t] + red_t[2][t] + red_t[3][t];
        meanv[b*NPIX + p0 + t] = ss * (1.0f / 64.0f);
        thick[b*NPIX + p0 + t] = 1.0f / (1.0f + __expf(-(tt + thick_b[0])));
    }
}

// ---------------- edge conv: 3x3, 1->64 ch, no bias, zero pad ----------------
__global__ void k_edge(const float* __restrict__ meanv, const float* __restrict__ edge_w,
                       float* __restrict__ edge)
{
    int idx = blockIdx.x * blockDim.x + threadIdx.x;
    if (idx >= BATCH * SKIPCH * NPIX) return;
    int p = idx & 4095, oc = (idx >> 12) & 63, b = idx >> 18;
    int y = p >> 6, x = p & 63;
    const float* mb = meanv + b * NPIX;
    const float* w = edge_w + oc * 9;
    float acc = 0.f;
    #pragma unroll
    for (int dy = -1; dy <= 1; dy++)
        #pragma unroll
        for (int dx = -1; dx <= 1; dx++) {
            int yy = y + dy, xx = x + dx;
            if ((unsigned)yy < 64u && (unsigned)xx < 64u)
                acc += mb[yy*64 + xx] * w[(dy+1)*3 + (dx+1)];
        }
    edge[idx] = acc;
}

// ---------------- pad off weights 18 -> 32 rows ----------------
__global__ void k_prep_offw(const float* __restrict__ off_w, const float* __restrict__ off_b,
                            float* __restrict__ wpad, float* __restrict__ bpad)
{
    int idx = blockIdx.x * blockDim.x + threadIdx.x;
    if (idx < 32 * 576) {
        int o = idx / 576, k = idx % 576;
        wpad[idx] = (o < 18) ? off_w[o*576 + k] : 0.f;
    }
    if (idx < 32) bpad[idx] = (idx < 18) ? off_b[idx] : 0.f;
}

// ---------------- off-GEMM with fused im2col ----------------
__global__ void __launch_bounds__(256) k_gemm_edge(
    const float* __restrict__ edge, const float* __restrict__ w,
    const float* __restrict__ bias, float* __restrict__ out)
{
    __shared__ __align__(16) float sh_in[32][128];
    __shared__ __align__(16) float sh_w[32][36];
    int b  = blockIdx.z;
    int n0 = blockIdx.x * 128;
    int t  = threadIdx.x;
    int tn = (t & 31) * 4;
    int to = (t >> 5) * 4;
    int kr = t >> 5;
    int kc = t & 31;
    int py = (n0 + tn) >> 6;
    int px = (n0 + tn) & 63;

    float acc[4][4] = {};
    float rin[4][4];
    float rw[4];

    #pragma unroll
    for (int i = 0; i < 4; i++) {
        int k = kr + i*8;
        int ic = k / 9, tap = k % 9;
        int dy = tap/3 - 1, dx = tap%3 - 1;
        const float* pc = edge + (((size_t)b*64 + ic) << 12);
        int yy = py + dy;
        bool yok = (unsigned)yy < 64u;
        #pragma unroll
        for (int j = 0; j < 4; j++) {
            int xx = px + j + dx;
            rin[i][j] = (yok && (unsigned)xx < 64u) ? pc[yy*64 + xx] : 0.f;
        }
    }
    #pragma unroll
    for (int i = 0; i < 4; i++)
        rw[i] = w[(size_t)(kr + i*8) * 576 + kc];

    for (int k0 = 0; k0 < 576; k0 += 32) {
        #pragma unroll
        for (int i = 0; i < 4; i++)
            *(float4*)&sh_in[kr + i*8][tn] = make_float4(rin[i][0], rin[i][1], rin[i][2], rin[i][3]);
        #pragma unroll
        for (int i = 0; i < 4; i++)
            sh_w[kc][kr + i*8] = rw[i];
        __syncthreads();

        int kn = k0 + 32;
        if (kn < 576) {
            #pragma unroll
            for (int i = 0; i < 4; i++) {
                int k = kn + kr + i*8;
                int ic = k / 9, tap = k % 9;
                int dy = tap/3 - 1, dx = tap%3 - 1;
                const float* pc = edge + (((size_t)b*64 + ic) << 12);
                int yy = py + dy;
                bool yok = (unsigned)yy < 64u;
                #pragma unroll
                for (int j = 0; j < 4; j++) {
                    int xx = px + j + dx;
                    rin[i][j] = (yok && (unsigned)xx < 64u) ? pc[yy*64 + xx] : 0.f;
                }
            }
            #pragma unroll
            for (int i = 0; i < 4; i++)
                rw[i] = w[(size_t)(kr + i*8) * 576 + kn + kc];
        }

        #pragma unroll
        for (int kk = 0; kk < 32; kk++) {
            float4 a  = *(float4*)&sh_in[kk][tn];
            float4 wv = *(float4*)&sh_w[kk][to];
            float av[4] = {a.x, a.y, a.z, a.w};
            float wr[4] = {wv.x, wv.y, wv.z, wv.w};
            #pragma unroll
            for (int i = 0; i < 4; i++)
                #pragma unroll
                for (int j = 0; j < 4; j++)
                    acc[i][j] += wr[i] * av[j];
        }
        __syncthreads();
    }

    #pragma unroll
    for (int i = 0; i < 4; i++) {
        int o = to + i;
        float bv = bias[o];
        float4 ov = {acc[i][0] + bv, acc[i][1] + bv, acc[i][2] + bv, acc[i][3] + bv};
        *(float4*)(out + (((size_t)b*32 + o) << 12) + n0 + tn) = ov;
    }
}

// ---------------- sample v2: guide fused, 8-channel groups ----------------
__global__ void __launch_bounds__(256) k_sample(
    const float* __restrict__ off, const float* __restrict__ thick,
    const float* __restrict__ skipu, float* __restrict__ col)
{
    int idx = blockIdx.x * blockDim.x + threadIdx.x;
    if (idx >= BATCH * 9 * 8 * NPIX) return;
    int p    = idx & 4095;
    int rest = idx >> 12;
    int g8   = rest & 7;  rest >>= 3;
    int k    = rest % 9;
    int b    = rest / 9;
    float guide = 1.f + 16.f * thick[b*NPIX + p];
    float dy = off[(((size_t)b*32 + 2*k    ) << 12) + p] * guide;
    float dx = off[(((size_t)b*32 + 2*k + 1) << 12) + p] * guide;
    float py = (float)(p >> 6) + (float)(k/3 - 1) + dy;
    float px = (float)(p & 63) + (float)(k%3 - 1) + dx;
    float y0f = floorf(py), x0f = floorf(px);
    float wy = py - y0f, wx = px - x0f;
    int y0 = (int)y0f, x0 = (int)x0f;
    int y1 = y0 + 1, x1 = x0 + 1;
    float vy0 = (y0 >= 0 && y0 < 64) ? 1.f : 0.f;
    float vy1 = (y1 >= 0 && y1 < 64) ? 1.f : 0.f;
    float vx0 = (x0 >= 0 && x0 < 64) ? 1.f : 0.f;
    float vx1 = (x1 >= 0 && x1 < 64) ? 1.f : 0.f;
    int y0c = min(max(y0,0),63), y1c = min(max(y1,0),63);
    int x0c = min(max(x0,0),63), x1c = min(max(x1,0),63);
    float w00 = (1.f-wy)*(1.f-wx)*vy0*vx0;
    float w01 = (1.f-wy)*wx      *vy0*vx1;
    float w10 = wy*(1.f-wx)      *vy1*vx0;
    float w11 = wy*wx            *vy1*vx1;
    int i00 = y0c*64+x0c, i01 = y0c*64+x1c, i10 = y1c*64+x0c, i11 = y1c*64+x1c;
    const float* sb = skipu + (size_t)b * SKIPCH * NPIX;
    #pragma unroll
    for (int i = 0; i < 8; i++) {
        int ic = g8*8 + i;
        const float* pc = sb + ic * NPIX;
        float v = w00*pc[i00] + w01*pc[i01] + w10*pc[i10] + w11*pc[i11];
        col[(((size_t)(b*64 + ic))*9 + k) * NPIX + p] = v;
    }
}

// ---------------- 1x1-conv GEMM v3: FFMA + register-prefetch double buffer ----------------
template<int TM>
__global__ void __launch_bounds__(256) k_gemm(
    const float* __restrict__ inA, const float* __restrict__ inB, int K, int K1,
    const float* __restrict__ w, const float* __restrict__ bias,
    const float* __restrict__ res, int act,
    float* __restrict__ out, int O)
{
    constexpr int OPT = TM / 8;
    __shared__ __align__(16) float sh_in[32][128];
    __shared__ __align__(16) float sh_w[32][TM + 4];

    int b  = blockIdx.z;
    int o0 = blockIdx.y * TM;
    int n0 = blockIdx.x * 128;
    int t  = threadIdx.x;
    int tn = (t & 31) * 4;
    int to = (t >> 5) * OPT;
    int kr = t >> 5;
    int kc = t & 31;
    int KB = K - K1;

    float acc[OPT][4] = {};
    float4 rin[4];
    float  rw[OPT];

    {
        #pragma unroll
        for (int i = 0; i < 4; i++) {
            int k = kr + i*8;
            const float* src = (k < K1)
                ? (inA + ((size_t)b*K1 + k) * NPIX)
                : (inB + ((size_t)b*KB + (k - K1)) * NPIX);
            rin[i] = *(const float4*)(src + n0 + tn);
        }
        #pragma unroll
        for (int i = 0; i < OPT; i++)
            rw[i] = w[(size_t)(o0 + kr + i*8) * K + kc];
    }

    for (int k0 = 0; k0 < K; k0 += 32) {
        #pragma unroll
        for (int i = 0; i < 4; i++)
            *(float4*)&sh_in[kr + i*8][tn] = rin[i];
        #pragma unroll
        for (int i = 0; i < OPT; i++)
            sh_w[kc][kr + i*8] = rw[i];
        __syncthreads();

        int kn = k0 + 32;
        if (kn < K) {
            #pragma unroll
            for (int i = 0; i < 4; i++) {
                int k = kn + kr + i*8;
                const float* src = (k < K1)
                    ? (inA + ((size_t)b*K1 + k) * NPIX)
                    : (inB + ((size_t)b*KB + (k - K1)) * NPIX);
                rin[i] = *(const float4*)(src + n0 + tn);
            }
            #pragma unroll
            for (int i = 0; i < OPT; i++)
                rw[i] = w[(size_t)(o0 + kr + i*8) * K + kn + kc];
        }

        #pragma unroll
        for (int kk = 0; kk < 32; kk++) {
            float4 a = *(float4*)&sh_in[kk][tn];
            float av[4] = {a.x, a.y, a.z, a.w};
            float wr[OPT];
            #pragma unroll
            for (int i = 0; i < OPT; i += 4) {
                float4 wv = *(float4*)&sh_w[kk][to + i];
                wr[i] = wv.x; wr[i+1] = wv.y; wr[i+2] = wv.z; wr[i+3] = wv.w;
            }
            #pragma unroll
            for (int i = 0; i < OPT; i++)
                #pragma unroll
                for (int j = 0; j < 4; j++)
                    acc[i][j] += wr[i] * av[j];
        }
        __syncthreads();
    }

    #pragma unroll
    for (int i = 0; i < OPT; i++) {
        int o = o0 + to + i;
        float bv = bias ? bias[o] : 0.f;
        float v[4];
        #pragma unroll
        for (int j = 0; j < 4; j++) v[j] = acc[i][j] + bv;
        if (act == 1) {
            #pragma unroll
            for (int j = 0; j < 4; j++) v[j] = gelu_f(v[j]);
        }
        size_t base = ((size_t)b*O + o) * NPIX + n0 + tn;
        if (res) {
            float4 r = *(const float4*)(res + base);
            v[0] += r.x; v[1] += r.y; v[2] += r.z; v[3] += r.w;
        }
        float4 ov = {v[0], v[1], v[2], v[3]};
        *(float4*)(out + base) = ov;
    }
}

// ---------------- tensor-core attention: N=4096, c=32, tf32 MMA ----------------
__global__ void __launch_bounds__(128) k_attn_tc(const float* __restrict__ qkv,
                                                 float* __restrict__ av)
{
    __shared__ float sQh[64][36];
    __shared__ float sQl[64][36];
    __shared__ float sKh[32][36];
    __shared__ float sKl[32][36];
    __shared__ float sV [32][36];
    __shared__ float sP [64][36];

    int b    = blockIdx.y;
    int n0   = blockIdx.x * 64;
    int t    = threadIdx.x;
    int warp = t >> 5, lane = t & 31;
    int gr   = lane >> 2;
    int tig  = lane & 3;
    int wrow = warp * 16;

    const float* qb = qkv + (size_t)b * 96 * NPIX;
    const float* kb = qb + 32 * NPIX;
    const float* vb = qb + 64 * NPIX;

    #pragma unroll
    for (int i = 0; i < 16; i++) {
        int flat = i * 128 + t;
        int c = flat >> 6, j = flat & 63;
        float v = qb[c*NPIX + n0 + j] * 0.17677669529663687f;
        float hi = tf32f(v);
        sQh[j][c] = hi;
        sQl[j][c] = tf32f(v - hi);
    }

    float o[4][4] = {};
    float l0 = 0.f, l1 = 0.f;

    for (int t0 = 0; t0 < NPIX; t0 += 32) {
        __syncthreads();
        #pragma unroll
        for (int i = 0; i < 8; i++) {
            int c = i * 4 + warp;
            float kv = kb[c*NPIX + t0 + lane];
            float hi = tf32f(kv);
            sKh[lane][c] = hi;
            sKl[lane][c] = tf32f(kv - hi);
            sV[c][lane]  = tf32f(vb[c*NPIX + t0 + lane]);
        }
        __syncthreads();

        float s[4][4] = {};
        #pragma unroll
        for (int k0 = 0; k0 < 32; k0 += 8) {
            float ah[4], al[4];
            ah[0] = sQh[wrow+gr  ][k0+tig];   ah[1] = sQh[wrow+gr+8][k0+tig];
            ah[2] = sQh[wrow+gr  ][k0+tig+4]; ah[3] = sQh[wrow+gr+8][k0+tig+4];
            al[0] = sQl[wrow+gr  ][k0+tig];   al[1] = sQl[wrow+gr+8][k0+tig];
            al[2] = sQl[wrow+gr  ][k0+tig+4]; al[3] = sQl[wrow+gr+8][k0+tig+4];
            #pragma unroll
            for (int nt = 0; nt < 4; nt++) {
                float bh0 = sKh[nt*8+gr][k0+tig], bh1 = sKh[nt*8+gr][k0+tig+4];
                float bl0 = sKl[nt*8+gr][k0+tig], bl1 = sKl[nt*8+gr][k0+tig+4];
                mma_tf32(s[nt], ah, bh0, bh1);
                mma_tf32(s[nt], ah, bl0, bl1);
                mma_tf32(s[nt], al, bh0, bh1);
            }
        }

        #pragma unroll
        for (int nt = 0; nt < 4; nt++) {
            float p0 = __expf(s[nt][0]);
            float p1 = __expf(s[nt][1]);
            float p2 = __expf(s[nt][2]);
            float p3 = __expf(s[nt][3]);
            l0 += p0 + p1;
            l1 += p2 + p3;
            sP[wrow+gr  ][nt*8 + 2*tig    ] = tf32f(p0);
            sP[wrow+gr  ][nt*8 + 2*tig + 1] = tf32f(p1);
            sP[wrow+gr+8][nt*8 + 2*tig    ] = tf32f(p2);
            sP[wrow+gr+8][nt*8 + 2*tig + 1] = tf32f(p3);
        }
        __syncwarp();

        #pragma unroll
        for (int k0 = 0; k0 < 32; k0 += 8) {
            float a[4];
            a[0] = sP[wrow+gr  ][k0+tig];   a[1] = sP[wrow+gr+8][k0+tig];
            a[2] = sP[wrow+gr  ][k0+tig+4]; a[3] = sP[wrow+gr+8][k0+tig+4];
            #pragma unroll
            for (int ct = 0; ct < 4; ct++) {
                float b0 = sV[ct*8+gr][k0+tig];
                float b1 = sV[ct*8+gr][k0+tig+4];
                mma_tf32(o[ct], a, b0, b1);
            }
        }
    }

    l0 += __shfl_xor_sync(0xffffffffu, l0, 1);
    l0 += __shfl_xor_sync(0xffffffffu, l0, 2);
    l1 += __shfl_xor_sync(0xffffffffu, l1, 1);
    l1 += __shfl_xor_sync(0xffffffffu, l1, 2);
    float inv0 = 1.f / l0, inv1 = 1.f / l1;

    __syncthreads();
    #pragma unroll
    for (int ct = 0; ct < 4; ct++) {
        sP[wrow+gr  ][ct*8 + 2*tig    ] = o[ct][0] * inv0;
        sP[wrow+gr  ][ct*8 + 2*tig + 1] = o[ct][1] * inv0;
        sP[wrow+gr+8][ct*8 + 2*tig    ] = o[ct][2] * inv1;
        sP[wrow+gr+8][ct*8 + 2*tig + 1] = o[ct][3] * inv1;
    }
    __syncthreads();

    #pragma unroll
    for (int i = 0; i < 16; i++) {
        int flat = i * 128 + t;
        int c = flat >> 6, j = flat & 63;
        av[((size_t)b*32 + c)*NPIX + n0 + j] = sP[j][c];
    }
}

// ---------------- LayerNorm v2: 64x64 tile per block, smem-staged ----------------
__global__ void __launch_bounds__(256) k_ln(
    const float* __restrict__ e, const float* __restrict__ g,
    const float* __restrict__ bta, float* __restrict__ outp)
{
    __shared__ float tile[64][65];
    __shared__ float rs[4][64], rs2[4][64];
    __shared__ float smu[64], srstd[64];
    int t  = threadIdx.x;
    int b  = blockIdx.x >> 6;
    int p0 = (blockIdx.x & 63) * 64;
    int pl = t & 63;
    int q  = t >> 6;
    float s = 0.f, s2 = 0.f;
    #pragma unroll 4
    for (int i = 0; i < 16; i++) {
        int c = q*16 + i;
        float v = e[(((size_t)b*64 + c) << 12) + p0 + pl];
        tile[c][pl] = v;
        s += v; s2 += v*v;
    }
    rs[q][pl] = s; rs2[q][pl] = s2;
    __syncthreads();
    if (t < 64) {
        float ss = rs[0][t] + rs[1][t] + rs[2][t] + rs[3][t];
        float qq = rs2[0][t] + rs2[1][t] + rs2[2][t] + rs2[3][t];
        float mu = ss * (1.f/64.f);
        float var = qq * (1.f/64.f) - mu*mu;
        smu[t] = mu;
        srstd[t] = rsqrtf(var + 1e-5f);
    }
    __syncthreads();
    float mu = smu[pl], rstd = srstd[pl];
    #pragma unroll 4
    for (int i = 0; i < 16; i++) {
        int c = q*16 + i;
        outp[(((size_t)b*64 + c) << 12) + p0 + pl] = (tile[c][pl] - mu)*rstd*g[c] + bta[c];
    }
}

// ---------------- depthwise 3x3 + gelu, smem-tiled: one (b,c) plane per block --------
__global__ void __launch_bounds__(256) k_dw(
    const float* __restrict__ h1, const float* __restrict__ w,
    const float* __restrict__ bias, float* __restrict__ h2)
{
    __shared__ float pl[64][65];
    int bc = blockIdx.x;
    int c  = bc & 255;
    int t  = threadIdx.x;
    const float* src = h1 + ((size_t)bc << 12);
    float* dst = h2 + ((size_t)bc << 12);

    #pragma unroll
    for (int i = 0; i < 4; i++) {
        int idx = i*256 + t;
        int y = idx >> 4, x4 = (idx & 15) * 4;
        float4 v = *(const float4*)(src + y*64 + x4);
        pl[y][x4] = v.x; pl[y][x4+1] = v.y; pl[y][x4+2] = v.z; pl[y][x4+3] = v.w;
    }
    __syncthreads();

    const float* wc = w + c * 9;
    float w0 = wc[0], w1 = wc[1], w2 = wc[2];
    float w3 = wc[3], w4 = wc[4], w5 = wc[5];
    float w6 = wc[6], w7 = wc[7], w8 = wc[8];
    float bv = bias[c];

    #pragma unroll
    for (int i = 0; i < 16; i++) {
        int p = i*256 + t;
        int y = p >> 6, x = p & 63;
        float acc = bv;
        if (y > 0) {
            if (x > 0)  acc += pl[y-1][x-1] * w0;
            acc += pl[y-1][x] * w1;
            if (x < 63) acc += pl[y-1][x+1] * w2;
        }
        if (x > 0)  acc += pl[y][x-1] * w3;
        acc += pl[y][x] * w4;
        if (x < 63) acc += pl[y][x+1] * w5;
        if (y < 63) {
            if (x > 0)  acc += pl[y+1][x-1] * w6;
            acc += pl[y+1][x] * w7;
            if (x < 63) acc += pl[y+1][x+1] * w8;
        }
        dst[p] = gelu_f(acc);
    }
}

// ---------------- host ----------------
extern "C" void kernel_launch(void* const* d_in, const int* in_sizes, int n_in,
                              void* d_out, int out_size)
{
    const float* x        = (const float*)d_in[0];
    const float* skip     = (const float*)d_in[1];
    const float* qkv_w    = (const float*)d_in[2];
    const float* qkv_b    = (const float*)d_in[3];
    const float* proj_w   = (const float*)d_in[4];
    const float* proj_b   = (const float*)d_in[5];
    const float* edge_w   = (const float*)d_in[6];
    const float* thick_w  = (const float*)d_in[7];
    const float* thick_b  = (const float*)d_in[8];
    const float* off_w    = (const float*)d_in[9];
    const float* off_b    = (const float*)d_in[10];
    const float* deform_w = (const float*)d_in[11];
    const float* deform_b = (const float*)d_in[12];
    const float* ln_g     = (const float*)d_in[13];
    const float* ln_b     = (const float*)d_in[14];
    const float* mlp1_w   = (const float*)d_in[15];
    const float* mlp1_b   = (const float*)d_in[16];
    const float* dw_w     = (const float*)d_in[17];
    const float* dw_b     = (const float*)d_in[18];
    const float* mlp2_w   = (const float*)d_in[19];
    const float* mlp2_b   = (const float*)d_in[20];
    const float* down_w   = (const float*)d_in[21];
    const float* down_b   = (const float*)d_in[22];
    const float* up_w     = (const float*)d_in[23];
    const float* up_b     = (const float*)d_in[24];
    float* out = (float*)d_out;

    float *skipu, *meanv, *thick, *qkv, *avb, *x2, *edge, *col, *off, *offw, *offb;
    float *dd, *e, *ln, *h1, *h2, *tt;
    cudaGetSymbolAddress((void**)&skipu, g_skipu);
    cudaGetSymbolAddress((void**)&meanv, g_mean);
    cudaGetSymbolAddress((void**)&thick, g_thick);
    cudaGetSymbolAddress((void**)&qkv,   g_qkv);
    cudaGetSymbolAddress((void**)&avb,   g_av);
    cudaGetSymbolAddress((void**)&x2,    g_x2);
    cudaGetSymbolAddress((void**)&edge,  g_edge);
    cudaGetSymbolAddress((void**)&col,   g_col);
    cudaGetSymbolAddress((void**)&off,   g_off);
    cudaGetSymbolAddress((void**)&offw,  g_offw);
    cudaGetSymbolAddress((void**)&offb,  g_offb);
    cudaGetSymbolAddress((void**)&dd,    g_d);
    cudaGetSymbolAddress((void**)&e,     g_e);
    cudaGetSymbolAddress((void**)&ln,    g_ln);
    cudaGetSymbolAddress((void**)&h1,    g_h1);
    cudaGetSymbolAddress((void**)&h2,    g_h2);
    cudaGetSymbolAddress((void**)&tt,    g_t);

    // attention branch
    k_gemm<32><<<dim3(32, 3, 4), 256>>>(x, nullptr, 256, 256, qkv_w, qkv_b, nullptr, 0, qkv, 96);
    k_attn_tc<<<dim3(64, 4), 128>>>(qkv, avb);
    k_gemm<64><<<dim3(32, 4, 4), 256>>>(avb, nullptr, 32, 32, proj_w, proj_b, x, 0, x2, 256);

    // skip branch
    k_upsample<<<256, 256>>>(skip, thick_w, thick_b, skipu, meanv, thick);
    k_edge<<<(BATCH*SKIPCH*NPIX + 255)/256, 256>>>(meanv, edge_w, edge);
    k_prep_offw<<<(32*576 + 255)/256, 256>>>(off_w, off_b, offw, offb);
    k_gemm_edge<<<dim3(32, 1, 4), 256>>>(edge, offw, offb, off);
    k_sample<<<(BATCH*9*8*NPIX + 255)/256, 256>>>(off, thick, skipu, col);
    k_gemm<64><<<dim3(32, 1, 4), 256>>>(col, nullptr, 576, 576, deform_w, deform_b, edge, 0, dd, 64);

    // merge + token mixer
    k_gemm<64><<<dim3(32, 1, 4), 256>>>(x2, dd, 320, 256, down_w, down_b, nullptr, 0, e, 64);
    k_ln<<<256, 256>>>(e, ln_g, ln_b, ln);
    k_gemm<64><<<dim3(32, 4, 4), 256>>>(ln, nullptr, 64, 64, mlp1_w, mlp1_b, nullptr, 1, h1, 256);
    k_dw<<<BATCH*256, 256>>>(h1, dw_w, dw_b, h2);
    k_gemm<64><<<dim3(32, 1, 4), 256>>>(h2, nullptr, 256, 256, mlp2_w, mlp2_b, e, 0, tt, 64);
    k_gemm<64><<<dim3(32, 4, 4), 256>>>(tt, nullptr, 64, 64, up_w, up_b, nullptr, 0, out, 256);
}

// round 17
// speedup vs baseline: 1.4353x; 1.0235x over previous
#include <cuda_runtime.h>
#include <math.h>

#define BATCH 4
#define INCH 256
#define SKIPCH 64
#define EMBEDC 64
#define NPIX 4096   // 64*64

// ---------------- scratch (static device globals; no allocation) ----------------
__device__ float g_skipu[BATCH*SKIPCH*NPIX];
__device__ float g_mean [BATCH*NPIX];
__device__ float g_thick[BATCH*NPIX];
__device__ float g_qkv  [BATCH*96*NPIX];
__device__ float g_av   [BATCH*32*NPIX];
__device__ float g_x2   [BATCH*INCH*NPIX];
__device__ float g_edge [BATCH*SKIPCH*NPIX];
__device__ float g_col  [BATCH*576*NPIX];
__device__ float g_off  [BATCH*32*NPIX];
__device__ float g_d    [BATCH*SKIPCH*NPIX];
__device__ float g_e    [BATCH*EMBEDC*NPIX];
__device__ float g_ln   [BATCH*EMBEDC*NPIX];
__device__ float g_h1   [BATCH*256*NPIX];
__device__ float g_h2   [BATCH*256*NPIX];
__device__ float g_t    [BATCH*EMBEDC*NPIX];

__device__ __forceinline__ float gelu_f(float v) {
    return 0.5f * v * (1.0f + erff(v * 0.70710678118654752f));
}

__device__ __forceinline__ float tf32f(float x) {
    unsigned u;
    asm("cvt.rna.tf32.f32 %0, %1;" : "=r"(u) : "f"(x));
    return __uint_as_float(u);
}

__device__ __forceinline__ void mma_tf32(float* d, const float* a, float b0, float b1) {
    asm volatile("mma.sync.aligned.m16n8k8.row.col.f32.tf32.tf32.f32 "
        "{%0,%1,%2,%3}, {%4,%5,%6,%7}, {%8,%9}, {%0,%1,%2,%3};"
        : "+f"(d[0]), "+f"(d[1]), "+f"(d[2]), "+f"(d[3])
        : "r"(__float_as_uint(a[0])), "r"(__float_as_uint(a[1])),
          "r"(__float_as_uint(a[2])), "r"(__float_as_uint(a[3])),
          "r"(__float_as_uint(b0)), "r"(__float_as_uint(b1)));
}

// ---------------- upsample v2: 64 pixels x 4 channel-groups per block ----------------
__global__ void __launch_bounds__(256) k_upsample(
    const float* __restrict__ skip, const float* __restrict__ thick_w,
    const float* __restrict__ thick_b,
    float* __restrict__ skipu, float* __restrict__ meanv, float* __restrict__ thick)
{
    __shared__ float red_s[4][64];
    __shared__ float red_t[4][64];
    int t  = threadIdx.x;
    int b  = blockIdx.x >> 6;
    int p0 = (blockIdx.x & 63) * 64;
    int pl = t & 63;
    int q  = t >> 6;
    int p  = p0 + pl;
    int oy = p >> 6, ox = p & 63;
    float sy = oy * 0.5f - 0.25f, sx = ox * 0.5f - 0.25f;
    float y0f = floorf(sy), x0f = floorf(sx);
    float wy = sy - y0f, wx = sx - x0f;
    int y0 = (int)y0f, x0 = (int)x0f;
    int y0c = min(max(y0, 0), 31), y1c = min(max(y0 + 1, 0), 31);
    int x0c = min(max(x0, 0), 31), x1c = min(max(x0 + 1, 0), 31);
    float w00 = (1.f - wy) * (1.f - wx), w01 = (1.f - wy) * wx;
    float w10 = wy * (1.f - wx), w11 = wy * wx;
    int i00 = y0c*32 + x0c, i01 = y0c*32 + x1c;
    int i10 = y1c*32 + x0c, i11 = y1c*32 + x1c;
    const float* sb = skip + (size_t)b * SKIPCH * 1024;
    float s = 0.f, ta = 0.f;
    #pragma unroll 4
    for (int i = 0; i < 16; i++) {
        int c = q*16 + i;
        const float* pc = sb + c * 1024;
        float v = w00*pc[i00] + w01*pc[i01] + w10*pc[i10] + w11*pc[i11];
        skipu[((size_t)(b*SKIPCH + c)) * NPIX + p] = v;
        s += v;
        ta += v * thick_w[c];
    }
    red_s[q][pl] = s; red_t[q][pl] = ta;
    __syncthreads();
    if (t < 64) {
        float ss = red_s[0][t] + red_s[1][t] + red_s[2][t] + red_s[3][t];
        float tt = red_t[0][t] + red_t[1][t] + red_t[2][t] + red_t[3][t];
        meanv[b*NPIX + p0 + t] = ss * (1.0f / 64.0f);
        thick[b*NPIX + p0 + t] = 1.0f / (1.0f + __expf(-(tt + thick_b[0])));
    }
}

// ---------------- edge conv: 3x3, 1->64 ch, no bias, zero pad ----------------
__global__ void k_edge(const float* __restrict__ meanv, const float* __restrict__ edge_w,
                       float* __restrict__ edge)
{
    int idx = blockIdx.x * blockDim.x + threadIdx.x;
    if (idx >= BATCH * SKIPCH * NPIX) return;
    int p = idx & 4095, oc = (idx >> 12) & 63, b = idx >> 18;
    int y = p >> 6, x = p & 63;
    const float* mb = meanv + b * NPIX;
    const float* w = edge_w + oc * 9;
    float acc = 0.f;
    #pragma unroll
    for (int dy = -1; dy <= 1; dy++)
        #pragma unroll
        for (int dx = -1; dx <= 1; dx++) {
            int yy = y + dy, xx = x + dx;
            if ((unsigned)yy < 64u && (unsigned)xx < 64u)
                acc += mb[yy*64 + xx] * w[(dy+1)*3 + (dx+1)];
        }
    edge[idx] = acc;
}

// ---------------- off-GEMM with fused im2col + fused weight padding ----------------
__global__ void __launch_bounds__(256) k_gemm_edge(
    const float* __restrict__ edge, const float* __restrict__ off_w,
    const float* __restrict__ off_b, float* __restrict__ out)
{
    __shared__ __align__(16) float sh_in[32][128];
    __shared__ __align__(16) float sh_w[32][36];
    int b  = blockIdx.z;
    int n0 = blockIdx.x * 128;
    int t  = threadIdx.x;
    int tn = (t & 31) * 4;
    int to = (t >> 5) * 4;
    int kr = t >> 5;
    int kc = t & 31;
    int py = (n0 + tn) >> 6;
    int px = (n0 + tn) & 63;

    float acc[4][4] = {};
    float rin[4][4];
    float rw[4];

    #pragma unroll
    for (int i = 0; i < 4; i++) {
        int k = kr + i*8;
        int ic = k / 9, tap = k % 9;
        int dy = tap/3 - 1, dx = tap%3 - 1;
        const float* pc = edge + (((size_t)b*64 + ic) << 12);
        int yy = py + dy;
        bool yok = (unsigned)yy < 64u;
        #pragma unroll
        for (int j = 0; j < 4; j++) {
            int xx = px + j + dx;
            rin[i][j] = (yok && (unsigned)xx < 64u) ? pc[yy*64 + xx] : 0.f;
        }
    }
    #pragma unroll
    for (int i = 0; i < 4; i++) {
        int o = kr + i*8;
        rw[i] = (o < 18) ? off_w[(size_t)o * 576 + kc] : 0.f;
    }

    for (int k0 = 0; k0 < 576; k0 += 32) {
        #pragma unroll
        for (int i = 0; i < 4; i++)
            *(float4*)&sh_in[kr + i*8][tn] = make_float4(rin[i][0], rin[i][1], rin[i][2], rin[i][3]);
        #pragma unroll
        for (int i = 0; i < 4; i++)
            sh_w[kc][kr + i*8] = rw[i];
        __syncthreads();

        int kn = k0 + 32;
        if (kn < 576) {
            #pragma unroll
            for (int i = 0; i < 4; i++) {
                int k = kn + kr + i*8;
                int ic = k / 9, tap = k % 9;
                int dy = tap/3 - 1, dx = tap%3 - 1;
                const float* pc = edge + (((size_t)b*64 + ic) << 12);
                int yy = py + dy;
                bool yok = (unsigned)yy < 64u;
                #pragma unroll
                for (int j = 0; j < 4; j++) {
                    int xx = px + j + dx;
                    rin[i][j] = (yok && (unsigned)xx < 64u) ? pc[yy*64 + xx] : 0.f;
                }
            }
            #pragma unroll
            for (int i = 0; i < 4; i++) {
                int o = kr + i*8;
                rw[i] = (o < 18) ? off_w[(size_t)o * 576 + kn + kc] : 0.f;
            }
        }

        #pragma unroll
        for (int kk = 0; kk < 32; kk++) {
            float4 a  = *(float4*)&sh_in[kk][tn];
            float4 wv = *(float4*)&sh_w[kk][to];
            float av[4] = {a.x, a.y, a.z, a.w};
            float wr[4] = {wv.x, wv.y, wv.z, wv.w};
            #pragma unroll
            for (int i = 0; i < 4; i++)
                #pragma unroll
                for (int j = 0; j < 4; j++)
                    acc[i][j] += wr[i] * av[j];
        }
        __syncthreads();
    }

    #pragma unroll
    for (int i = 0; i < 4; i++) {
        int o = to + i;
        float bv = (o < 18) ? off_b[o] : 0.f;
        float4 ov = {acc[i][0] + bv, acc[i][1] + bv, acc[i][2] + bv, acc[i][3] + bv};
        *(float4*)(out + (((size_t)b*32 + o) << 12) + n0 + tn) = ov;
    }
}

// ---------------- sample v2: guide fused, 8-channel groups ----------------
__global__ void __launch_bounds__(256) k_sample(
    const float* __restrict__ off, const float* __restrict__ thick,
    const float* __restrict__ skipu, float* __restrict__ col)
{
    int idx = blockIdx.x * blockDim.x + threadIdx.x;
    if (idx >= BATCH * 9 * 8 * NPIX) return;
    int p    = idx & 4095;
    int rest = idx >> 12;
    int g8   = rest & 7;  rest >>= 3;
    int k    = rest % 9;
    int b    = rest / 9;
    float guide = 1.f + 16.f * thick[b*NPIX + p];
    float dy = off[(((size_t)b*32 + 2*k    ) << 12) + p] * guide;
    float dx = off[(((size_t)b*32 + 2*k + 1) << 12) + p] * guide;
    float py = (float)(p >> 6) + (float)(k/3 - 1) + dy;
    float px = (float)(p & 63) + (float)(k%3 - 1) + dx;
    float y0f = floorf(py), x0f = floorf(px);
    float wy = py - y0f, wx = px - x0f;
    int y0 = (int)y0f, x0 = (int)x0f;
    int y1 = y0 + 1, x1 = x0 + 1;
    float vy0 = (y0 >= 0 && y0 < 64) ? 1.f : 0.f;
    float vy1 = (y1 >= 0 && y1 < 64) ? 1.f : 0.f;
    float vx0 = (x0 >= 0 && x0 < 64) ? 1.f : 0.f;
    float vx1 = (x1 >= 0 && x1 < 64) ? 1.f : 0.f;
    int y0c = min(max(y0,0),63), y1c = min(max(y1,0),63);
    int x0c = min(max(x0,0),63), x1c = min(max(x1,0),63);
    float w00 = (1.f-wy)*(1.f-wx)*vy0*vx0;
    float w01 = (1.f-wy)*wx      *vy0*vx1;
    float w10 = wy*(1.f-wx)      *vy1*vx0;
    float w11 = wy*wx            *vy1*vx1;
    int i00 = y0c*64+x0c, i01 = y0c*64+x1c, i10 = y1c*64+x0c, i11 = y1c*64+x1c;
    const float* sb = skipu + (size_t)b * SKIPCH * NPIX;
    #pragma unroll
    for (int i = 0; i < 8; i++) {
        int ic = g8*8 + i;
        const float* pc = sb + ic * NPIX;
        float v = w00*pc[i00] + w01*pc[i01] + w10*pc[i10] + w11*pc[i11];
        col[(((size_t)(b*64 + ic))*9 + k) * NPIX + p] = v;
    }
}

// ---------------- 1x1-conv GEMM v3: FFMA + register-prefetch double buffer ----------------
template<int TM>
__global__ void __launch_bounds__(256) k_gemm(
    const float* __restrict__ inA, const float* __restrict__ inB, int K, int K1,
    const float* __restrict__ w, const float* __restrict__ bias,
    const float* __restrict__ res, int act,
    float* __restrict__ out, int O)
{
    constexpr int OPT = TM / 8;
    __shared__ __align__(16) float sh_in[32][128];
    __shared__ __align__(16) float sh_w[32][TM + 4];

    int b  = blockIdx.z;
    int o0 = blockIdx.y * TM;
    int n0 = blockIdx.x * 128;
    int t  = threadIdx.x;
    int tn = (t & 31) * 4;
    int to = (t >> 5) * OPT;
    int kr = t >> 5;
    int kc = t & 31;
    int KB = K - K1;

    float acc[OPT][4] = {};
    float4 rin[4];
    float  rw[OPT];

    {
        #pragma unroll
        for (int i = 0; i < 4; i++) {
            int k = kr + i*8;
            const float* src = (k < K1)
                ? (inA + ((size_t)b*K1 + k) * NPIX)
                : (inB + ((size_t)b*KB + (k - K1)) * NPIX);
            rin[i] = *(const float4*)(src + n0 + tn);
        }
        #pragma unroll
        for (int i = 0; i < OPT; i++)
            rw[i] = w[(size_t)(o0 + kr + i*8) * K + kc];
    }

    for (int k0 = 0; k0 < K; k0 += 32) {
        #pragma unroll
        for (int i = 0; i < 4; i++)
            *(float4*)&sh_in[kr + i*8][tn] = rin[i];
        #pragma unroll
        for (int i = 0; i < OPT; i++)
            sh_w[kc][kr + i*8] = rw[i];
        __syncthreads();

        int kn = k0 + 32;
        if (kn < K) {
            #pragma unroll
            for (int i = 0; i < 4; i++) {
                int k = kn + kr + i*8;
                const float* src = (k < K1)
                    ? (inA + ((size_t)b*K1 + k) * NPIX)
                    : (inB + ((size_t)b*KB + (k - K1)) * NPIX);
                rin[i] = *(const float4*)(src + n0 + tn);
            }
            #pragma unroll
            for (int i = 0; i < OPT; i++)
                rw[i] = w[(size_t)(o0 + kr + i*8) * K + kn + kc];
        }

        #pragma unroll
        for (int kk = 0; kk < 32; kk++) {
            float4 a = *(float4*)&sh_in[kk][tn];
            float av[4] = {a.x, a.y, a.z, a.w};
            float wr[OPT];
            #pragma unroll
            for (int i = 0; i < OPT; i += 4) {
                float4 wv = *(float4*)&sh_w[kk][to + i];
                wr[i] = wv.x; wr[i+1] = wv.y; wr[i+2] = wv.z; wr[i+3] = wv.w;
            }
            #pragma unroll
            for (int i = 0; i < OPT; i++)
                #pragma unroll
                for (int j = 0; j < 4; j++)
                    acc[i][j] += wr[i] * av[j];
        }
        __syncthreads();
    }

    #pragma unroll
    for (int i = 0; i < OPT; i++) {
        int o = o0 + to + i;
        float bv = bias ? bias[o] : 0.f;
        float v[4];
        #pragma unroll
        for (int j = 0; j < 4; j++) v[j] = acc[i][j] + bv;
        if (act == 1) {
            #pragma unroll
            for (int j = 0; j < 4; j++) v[j] = gelu_f(v[j]);
        }
        size_t base = ((size_t)b*O + o) * NPIX + n0 + tn;
        if (res) {
            float4 r = *(const float4*)(res + base);
            v[0] += r.x; v[1] += r.y; v[2] += r.z; v[3] += r.w;
        }
        float4 ov = {v[0], v[1], v[2], v[3]};
        *(float4*)(out + base) = ov;
    }
}

// ---------------- down-GEMM with fused LayerNorm ----------------
// K=320 (x2 256ch + dd 64ch) -> 64 out channels, all in one block (TM=64).
// Epilogue: per-pixel mean/var over 64 channels via smem reduce, writes e AND ln.
__global__ void __launch_bounds__(256) k_gemm_down_ln(
    const float* __restrict__ inA, const float* __restrict__ inB,
    const float* __restrict__ w, const float* __restrict__ bias,
    const float* __restrict__ ln_g, const float* __restrict__ ln_b,
    float* __restrict__ e_out, float* __restrict__ ln_out)
{
    constexpr int K = 320, K1 = 256, KB = 64, OPT = 8;
    __shared__ __align__(16) float sh_in[32][128];
    __shared__ __align__(16) float sh_w[32][68];
    __shared__ float red_s[4][8][33];
    __shared__ float red_q[4][8][33];
    __shared__ float smu[128], srstd[128];

    int b  = blockIdx.z;
    int n0 = blockIdx.x * 128;
    int t  = threadIdx.x;
    int tn = (t & 31) * 4;
    int to = (t >> 5) * OPT;
    int kr = t >> 5;
    int kc = t & 31;
    int tog = t >> 5;      // 0..7
    int tng = t & 31;      // 0..31

    float acc[OPT][4] = {};
    float4 rin[4];
    float  rw[OPT];

    {
        #pragma unroll
        for (int i = 0; i < 4; i++) {
            int k = kr + i*8;
            const float* src = (k < K1)
                ? (inA + ((size_t)b*K1 + k) * NPIX)
                : (inB + ((size_t)b*KB + (k - K1)) * NPIX);
            rin[i] = *(const float4*)(src + n0 + tn);
        }
        #pragma unroll
        for (int i = 0; i < OPT; i++)
            rw[i] = w[(size_t)(kr + i*8) * K + kc];
    }

    for (int k0 = 0; k0 < K; k0 += 32) {
        #pragma unroll
        for (int i = 0; i < 4; i++)
            *(float4*)&sh_in[kr + i*8][tn] = rin[i];
        #pragma unroll
        for (int i = 0; i < OPT; i++)
            sh_w[kc][kr + i*8] = rw[i];
        __syncthreads();

        int kn = k0 + 32;
        if (kn < K) {
            #pragma unroll
            for (int i = 0; i < 4; i++) {
                int k = kn + kr + i*8;
                const float* src = (k < K1)
                    ? (inA + ((size_t)b*K1 + k) * NPIX)
                    : (inB + ((size_t)b*KB + (k - K1)) * NPIX);
                rin[i] = *(const float4*)(src + n0 + tn);
            }
            #pragma unroll
            for (int i = 0; i < OPT; i++)
                rw[i] = w[(size_t)(kr + i*8) * K + kn + kc];
        }

        #pragma unroll
        for (int kk = 0; kk < 32; kk++) {
            float4 a = *(float4*)&sh_in[kk][tn];
            float av[4] = {a.x, a.y, a.z, a.w};
            float wr[OPT];
            #pragma unroll
            for (int i = 0; i < OPT; i += 4) {
                float4 wv = *(float4*)&sh_w[kk][to + i];
                wr[i] = wv.x; wr[i+1] = wv.y; wr[i+2] = wv.z; wr[i+3] = wv.w;
            }
            #pragma unroll
            for (int i = 0; i < OPT; i++)
                #pragma unroll
                for (int j = 0; j < 4; j++)
                    acc[i][j] += wr[i] * av[j];
        }
        __syncthreads();
    }

    // epilogue: e = acc + bias; write e; partial sums for LN
    float v[OPT][4];
    float ps[4] = {0.f, 0.f, 0.f, 0.f};
    float pq[4] = {0.f, 0.f, 0.f, 0.f};
    #pragma unroll
    for (int i = 0; i < OPT; i++) {
        int o = to + i;
        float bv = bias[o];
        size_t base = ((size_t)b*64 + o) * NPIX + n0 + tn;
        #pragma unroll
        for (int j = 0; j < 4; j++) {
            float vv = acc[i][j] + bv;
            v[i][j] = vv;
            ps[j] += vv;
            pq[j] += vv * vv;
        }
        float4 ov = {v[i][0], v[i][1], v[i][2], v[i][3]};
        *(float4*)(e_out + base) = ov;
    }
    #pragma unroll
    for (int j = 0; j < 4; j++) {
        red_s[j][tog][tng] = ps[j];
        red_q[j][tog][tng] = pq[j];
    }
    __syncthreads();
    if (t < 128) {
        int j = t & 3, png = t >> 2;
        float ss = 0.f, qq = 0.f;
        #pragma unroll
        for (int g = 0; g < 8; g++) {
            ss += red_s[j][g][png];
            qq += red_q[j][g][png];
        }
        float mu = ss * (1.f/64.f);
        float var = qq * (1.f/64.f) - mu*mu;
        smu[png*4 + j]   = mu;
        srstd[png*4 + j] = rsqrtf(var + 1e-5f);
    }
    __syncthreads();
    float mu[4], rstd[4];
    #pragma unroll
    for (int j = 0; j < 4; j++) {
        mu[j]   = smu[tng*4 + j];
        rstd[j] = srstd[tng*4 + j];
    }
    #pragma unroll
    for (int i = 0; i < OPT; i++) {
        int o = to + i;
        float gg = ln_g[o], bb = ln_b[o];
        size_t base = ((size_t)b*64 + o) * NPIX + n0 + tn;
        float4 ov;
        ov.x = (v[i][0] - mu[0]) * rstd[0] * gg + bb;
        ov.y = (v[i][1] - mu[1]) * rstd[1] * gg + bb;
        ov.z = (v[i][2] - mu[2]) * rstd[2] * gg + bb;
        ov.w = (v[i][3] - mu[3]) * rstd[3] * gg + bb;
        *(float4*)(ln_out + base) = ov;
    }
}

// ---------------- tensor-core attention: N=4096, c=32, tf32 MMA ----------------
__global__ void __launch_bounds__(128) k_attn_tc(const float* __restrict__ qkv,
                                                 float* __restrict__ av)
{
    __shared__ float sQh[64][36];
    __shared__ float sQl[64][36];
    __shared__ float sKh[32][36];
    __shared__ float sKl[32][36];
    __shared__ float sV [32][36];
    __shared__ float sP [64][36];

    int b    = blockIdx.y;
    int n0   = blockIdx.x * 64;
    int t    = threadIdx.x;
    int warp = t >> 5, lane = t & 31;
    int gr   = lane >> 2;
    int tig  = lane & 3;
    int wrow = warp * 16;

    const float* qb = qkv + (size_t)b * 96 * NPIX;
    const float* kb = qb + 32 * NPIX;
    const float* vb = qb + 64 * NPIX;

    #pragma unroll
    for (int i = 0; i < 16; i++) {
        int flat = i * 128 + t;
        int c = flat >> 6, j = flat & 63;
        float v = qb[c*NPIX + n0 + j] * 0.17677669529663687f;
        float hi = tf32f(v);
        sQh[j][c] = hi;
        sQl[j][c] = tf32f(v - hi);
    }

    float o[4][4] = {};
    float l0 = 0.f, l1 = 0.f;

    for (int t0 = 0; t0 < NPIX; t0 += 32) {
        __syncthreads();
        #pragma unroll
        for (int i = 0; i < 8; i++) {
            int c = i * 4 + warp;
            float kv = kb[c*NPIX + t0 + lane];
            float hi = tf32f(kv);
            sKh[lane][c] = hi;
            sKl[lane][c] = tf32f(kv - hi);
            sV[c][lane]  = tf32f(vb[c*NPIX + t0 + lane]);
        }
        __syncthreads();

        float s[4][4] = {};
        #pragma unroll
        for (int k0 = 0; k0 < 32; k0 += 8) {
            float ah[4], al[4];
            ah[0] = sQh[wrow+gr  ][k0+tig];   ah[1] = sQh[wrow+gr+8][k0+tig];
            ah[2] = sQh[wrow+gr  ][k0+tig+4]; ah[3] = sQh[wrow+gr+8][k0+tig+4];
            al[0] = sQl[wrow+gr  ][k0+tig];   al[1] = sQl[wrow+gr+8][k0+tig];
            al[2] = sQl[wrow+gr  ][k0+tig+4]; al[3] = sQl[wrow+gr+8][k0+tig+4];
            #pragma unroll
            for (int nt = 0; nt < 4; nt++) {
                float bh0 = sKh[nt*8+gr][k0+tig], bh1 = sKh[nt*8+gr][k0+tig+4];
                float bl0 = sKl[nt*8+gr][k0+tig], bl1 = sKl[nt*8+gr][k0+tig+4];
                mma_tf32(s[nt], ah, bh0, bh1);
                mma_tf32(s[nt], ah, bl0, bl1);
                mma_tf32(s[nt], al, bh0, bh1);
            }
        }

        #pragma unroll
        for (int nt = 0; nt < 4; nt++) {
            float p0 = __expf(s[nt][0]);
            float p1 = __expf(s[nt][1]);
            float p2 = __expf(s[nt][2]);
            float p3 = __expf(s[nt][3]);
            l0 += p0 + p1;
            l1 += p2 + p3;
            sP[wrow+gr  ][nt*8 + 2*tig    ] = tf32f(p0);
            sP[wrow+gr  ][nt*8 + 2*tig + 1] = tf32f(p1);
            sP[wrow+gr+8][nt*8 + 2*tig    ] = tf32f(p2);
            sP[wrow+gr+8][nt*8 + 2*tig + 1] = tf32f(p3);
        }
        __syncwarp();

        #pragma unroll
        for (int k0 = 0; k0 < 32; k0 += 8) {
            float a[4];
            a[0] = sP[wrow+gr  ][k0+tig];   a[1] = sP[wrow+gr+8][k0+tig];
            a[2] = sP[wrow+gr  ][k0+tig+4]; a[3] = sP[wrow+gr+8][k0+tig+4];
            #pragma unroll
            for (int ct = 0; ct < 4; ct++) {
                float b0 = sV[ct*8+gr][k0+tig];
                float b1 = sV[ct*8+gr][k0+tig+4];
                mma_tf32(o[ct], a, b0, b1);
            }
        }
    }

    l0 += __shfl_xor_sync(0xffffffffu, l0, 1);
    l0 += __shfl_xor_sync(0xffffffffu, l0, 2);
    l1 += __shfl_xor_sync(0xffffffffu, l1, 1);
    l1 += __shfl_xor_sync(0xffffffffu, l1, 2);
    float inv0 = 1.f / l0, inv1 = 1.f / l1;

    __syncthreads();
    #pragma unroll
    for (int ct = 0; ct < 4; ct++) {
        sP[wrow+gr  ][ct*8 + 2*tig    ] = o[ct][0] * inv0;
        sP[wrow+gr  ][ct*8 + 2*tig + 1] = o[ct][1] * inv0;
        sP[wrow+gr+8][ct*8 + 2*tig    ] = o[ct][2] * inv1;
        sP[wrow+gr+8][ct*8 + 2*tig + 1] = o[ct][3] * inv1;
    }
    __syncthreads();

    #pragma unroll
    for (int i = 0; i < 16; i++) {
        int flat = i * 128 + t;
        int c = flat >> 6, j = flat & 63;
        av[((size_t)b*32 + c)*NPIX + n0 + j] = sP[j][c];
    }
}

// ---------------- depthwise 3x3 + gelu, smem-tiled: one (b,c) plane per block --------
__global__ void __launch_bounds__(256) k_dw(
    const float* __restrict__ h1, const float* __restrict__ w,
    const float* __restrict__ bias, float* __restrict__ h2)
{
    __shared__ float pl[64][65];
    int bc = blockIdx.x;
    int c  = bc & 255;
    int t  = threadIdx.x;
    const float* src = h1 + ((size_t)bc << 12);
    float* dst = h2 + ((size_t)bc << 12);

    #pragma unroll
    for (int i = 0; i < 4; i++) {
        int idx = i*256 + t;
        int y = idx >> 4, x4 = (idx & 15) * 4;
        float4 v = *(const float4*)(src + y*64 + x4);
        pl[y][x4] = v.x; pl[y][x4+1] = v.y; pl[y][x4+2] = v.z; pl[y][x4+3] = v.w;
    }
    __syncthreads();

    const float* wc = w + c * 9;
    float w0 = wc[0], w1 = wc[1], w2 = wc[2];
    float w3 = wc[3], w4 = wc[4], w5 = wc[5];
    float w6 = wc[6], w7 = wc[7], w8 = wc[8];
    float bv = bias[c];

    #pragma unroll
    for (int i = 0; i < 16; i++) {
        int p = i*256 + t;
        int y = p >> 6, x = p & 63;
        float acc = bv;
        if (y > 0) {
            if (x > 0)  acc += pl[y-1][x-1] * w0;
            acc += pl[y-1][x] * w1;
            if (x < 63) acc += pl[y-1][x+1] * w2;
        }
        if (x > 0)  acc += pl[y][x-1] * w3;
        acc += pl[y][x] * w4;
        if (x < 63) acc += pl[y][x+1] * w5;
        if (y < 63) {
            if (x > 0)  acc += pl[y+1][x-1] * w6;
            acc += pl[y+1][x] * w7;
            if (x < 63) acc += pl[y+1][x+1] * w8;
        }
        dst[p] = gelu_f(acc);
    }
}

// ---------------- host ----------------
extern "C" void kernel_launch(void* const* d_in, const int* in_sizes, int n_in,
                              void* d_out, int out_size)
{
    const float* x        = (const float*)d_in[0];
    const float* skip     = (const float*)d_in[1];
    const float* qkv_w    = (const float*)d_in[2];
    const float* qkv_b    = (const float*)d_in[3];
    const float* proj_w   = (const float*)d_in[4];
    const float* proj_b   = (const float*)d_in[5];
    const float* edge_w   = (const float*)d_in[6];
    const float* thick_w  = (const float*)d_in[7];
    const float* thick_b  = (const float*)d_in[8];
    const float* off_w    = (const float*)d_in[9];
    const float* off_b    = (const float*)d_in[10];
    const float* deform_w = (const float*)d_in[11];
    const float* deform_b = (const float*)d_in[12];
    const float* ln_g     = (const float*)d_in[13];
    const float* ln_b     = (const float*)d_in[14];
    const float* mlp1_w   = (const float*)d_in[15];
    const float* mlp1_b   = (const float*)d_in[16];
    const float* dw_w     = (const float*)d_in[17];
    const float* dw_b     = (const float*)d_in[18];
    const float* mlp2_w   = (const float*)d_in[19];
    const float* mlp2_b   = (const float*)d_in[20];
    const float* down_w   = (const float*)d_in[21];
    const float* down_b   = (const float*)d_in[22];
    const float* up_w     = (const float*)d_in[23];
    const float* up_b     = (const float*)d_in[24];
    float* out = (float*)d_out;

    float *skipu, *meanv, *thick, *qkv, *avb, *x2, *edge, *col, *off;
    float *dd, *e, *ln, *h1, *h2, *tt;
    cudaGetSymbolAddress((void**)&skipu, g_skipu);
    cudaGetSymbolAddress((void**)&meanv, g_mean);
    cudaGetSymbolAddress((void**)&thick, g_thick);
    cudaGetSymbolAddress((void**)&qkv,   g_qkv);
    cudaGetSymbolAddress((void**)&avb,   g_av);
    cudaGetSymbolAddress((void**)&x2,    g_x2);
    cudaGetSymbolAddress((void**)&edge,  g_edge);
    cudaGetSymbolAddress((void**)&col,   g_col);
    cudaGetSymbolAddress((void**)&off,   g_off);
    cudaGetSymbolAddress((void**)&dd,    g_d);
    cudaGetSymbolAddress((void**)&e,     g_e);
    cudaGetSymbolAddress((void**)&ln,    g_ln);
    cudaGetSymbolAddress((void**)&h1,    g_h1);
    cudaGetSymbolAddress((void**)&h2,    g_h2);
    cudaGetSymbolAddress((void**)&tt,    g_t);

    // attention branch
    k_gemm<32><<<dim3(32, 3, 4), 256>>>(x, nullptr, 256, 256, qkv_w, qkv_b, nullptr, 0, qkv, 96);
    k_attn_tc<<<dim3(64, 4), 128>>>(qkv, avb);
    k_gemm<64><<<dim3(32, 4, 4), 256>>>(avb, nullptr, 32, 32, proj_w, proj_b, x, 0, x2, 256);

    // skip branch
    k_upsample<<<256, 256>>>(skip, thick_w, thick_b, skipu, meanv, thick);
    k_edge<<<(BATCH*SKIPCH*NPIX + 255)/256, 256>>>(meanv, edge_w, edge);
    k_gemm_edge<<<dim3(32, 1, 4), 256>>>(edge, off_w, off_b, off);
    k_sample<<<(BATCH*9*8*NPIX + 255)/256, 256>>>(off, thick, skipu, col);
    k_gemm<64><<<dim3(32, 1, 4), 256>>>(col, nullptr, 576, 576, deform_w, deform_b, edge, 0, dd, 64);

    // merge + token mixer (LN fused into down-GEMM)
    k_gemm_down_ln<<<dim3(32, 1, 4), 256>>>(x2, dd, down_w, down_b, ln_g, ln_b, e, ln);
    k_gemm<64><<<dim3(32, 4, 4), 256>>>(ln, nullptr, 64, 64, mlp1_w, mlp1_b, nullptr, 1, h1, 256);
    k_dw<<<BATCH*256, 256>>>(h1, dw_w, dw_b, h2);
    k_gemm<64><<<dim3(32, 1, 4), 256>>>(h2, nullptr, 256, 256, mlp2_w, mlp2_b, e, 0, tt, 64);
    k_gemm<64><<<dim3(32, 4, 4), 256>>>(tt, nullptr, 64, 64, up_w, up_b, nullptr, 0, out, 256);
}